// round 3
// baseline (speedup 1.0000x reference)
#include <cuda_runtime.h>
#include <math.h>
#include <stdint.h>

#define Bc   4
#define Nc   4096
#define Kc   20
#define BN   (Bc*Nc)          // 16384
#define VEPS 1e-6f
#define BNEPS 1e-5f

// ---------------- persistent device scratch (no allocations allowed) -------
__device__ int    g_idx[Bc*Nc*Kc];
__device__ float  g_bufA[BN*3*128];
__device__ float  g_bufB[BN*4*128];      // padded (4 rows/point) for conv5 MMA
__device__ float  g_p[BN*3*128];
__device__ float  g_d[BN*3*128];
__device__ double g_s1[128];
__device__ double g_s2[128];
__device__ double g_s3[128];
__device__ double g_s4[256];
__device__ double g_s5[2048];            // conv5 norm sums (1024 + 1024)
__device__ float  g_sumv [Bc*1024*3];
__device__ float  g_sumvn[Bc*1024*3];
__device__ float  g_mu[1024];
__device__ float  g_rstd[1024];

// ---------------------------------------------------------------------------
__global__ void zero_stats() {
    int i = blockIdx.x * 256 + threadIdx.x;          // grid 48*256 = 12288
    if (i < 128) { g_s1[i] = 0.0; g_s2[i] = 0.0; g_s3[i] = 0.0; }
    if (i < 256) { g_s4[i] = 0.0; }
    if (i < 2048){ g_s5[i] = 0.0; }
    g_sumv[i]  = 0.f;
    g_sumvn[i] = 0.f;
}

// ===================== mma.sync helpers ======================================
__device__ __forceinline__ uint32_t f2tf32(float f) {
    uint32_t r; asm("cvt.rna.tf32.f32 %0, %1;" : "=r"(r) : "f"(f)); return r;
}
__device__ __forceinline__ void mma16n8k8(float* c, const uint32_t* a, const uint32_t* b) {
    asm volatile("mma.sync.aligned.m16n8k8.row.col.f32.tf32.tf32.f32 "
        "{%0,%1,%2,%3}, {%4,%5,%6,%7}, {%8,%9}, {%0,%1,%2,%3};"
        : "+f"(c[0]), "+f"(c[1]), "+f"(c[2]), "+f"(c[3])
        : "r"(a[0]), "r"(a[1]), "r"(a[2]), "r"(a[3]), "r"(b[0]), "r"(b[1]));
}

// --------------------------- KNN (top-20 by -dist) --------------------------
__global__ __launch_bounds__(256) void knn_kernel(const float* __restrict__ x) {
    int b  = blockIdx.y;
    int n0 = blockIdx.x * 2;
    __shared__ float dist[2][Nc];
    __shared__ float rv[256];
    __shared__ int   ri[256];
    const float* xb = x + (size_t)b * Nc * 3;

    float q0x = xb[n0*3+0],     q0y = xb[n0*3+1],     q0z = xb[n0*3+2];
    float q1x = xb[(n0+1)*3+0], q1y = xb[(n0+1)*3+1], q1z = xb[(n0+1)*3+2];
    float sq0 = q0x*q0x + q0y*q0y + q0z*q0z;
    float sq1 = q1x*q1x + q1y*q1y + q1z*q1z;

    for (int j = threadIdx.x; j < Nc; j += 256) {
        float ax = xb[j*3+0], ay = xb[j*3+1], az = xb[j*3+2];
        float sqj = ax*ax + ay*ay + az*az;
        dist[0][j] = 2.f*(q0x*ax + q0y*ay + q0z*az) - sq0 - sqj;
        dist[1][j] = 2.f*(q1x*ax + q1y*ay + q1z*az) - sq1 - sqj;
    }
    __syncthreads();

    int half = threadIdx.x >> 7;
    int lt   = threadIdx.x & 127;
    float* dh = dist[half];
    int n = n0 + half;

    for (int k = 0; k < Kc; k++) {
        float best = -3.3e38f; int bi = Nc;
        for (int j = lt; j < Nc; j += 128) {
            float v = dh[j];
            if (v > best) { best = v; bi = j; }
        }
        rv[threadIdx.x] = best; ri[threadIdx.x] = bi;
        __syncthreads();
        #pragma unroll
        for (int s = 64; s > 0; s >>= 1) {
            if (lt < s) {
                float ov = rv[threadIdx.x + s]; int oi = ri[threadIdx.x + s];
                float mv = rv[threadIdx.x];     int mi = ri[threadIdx.x];
                if (ov > mv || (ov == mv && oi < mi)) { rv[threadIdx.x] = ov; ri[threadIdx.x] = oi; }
            }
            __syncthreads();
        }
        if (lt == 0) {
            int w = ri[threadIdx.x];
            g_idx[((size_t)b*Nc + n)*Kc + k] = w;
            dh[w] = -3.4e38f;
        }
        __syncthreads();
    }
}

// --------------------------- block1 (3ch edge feat -> 64) -------------------
__device__ __forceinline__ void build_f(const float* __restrict__ x, int b, int n0,
                                        float f[2][Kc][9]) {
    int t = threadIdx.x;
    if (t < 2*Kc) {
        int ln = t / Kc, k = t % Kc;
        int n = n0 + ln;
        const float* xb = x + (size_t)b * Nc * 3;
        float cx = xb[n*3+0], cy = xb[n*3+1], cz = xb[n*3+2];
        int j = g_idx[((size_t)b*Nc + n)*Kc + k];
        float ax = xb[j*3+0], ay = xb[j*3+1], az = xb[j*3+2];
        f[ln][k][0] = ax - cx; f[ln][k][1] = ay - cy; f[ln][k][2] = az - cz;
        f[ln][k][3] = cx;      f[ln][k][4] = cy;      f[ln][k][5] = cz;
        f[ln][k][6] = ay*cz - az*cy;
        f[ln][k][7] = az*cx - ax*cz;
        f[ln][k][8] = ax*cy - ay*cx;
    }
}

__global__ __launch_bounds__(128) void block1_stats(const float* __restrict__ x,
                                                    const float* __restrict__ W1) {
    int b = blockIdx.y, n0 = blockIdx.x * 2;
    __shared__ float f[2][Kc][9];
    __shared__ float red[2][128];
    build_f(x, b, n0, f);
    __syncthreads();
    int t = threadIdx.x;
    int ln = t >> 6, c = t & 63;
    float w0 = W1[c*3+0], w1 = W1[c*3+1], w2 = W1[c*3+2];
    float sn = 0.f, sn2 = 0.f;
    #pragma unroll
    for (int k = 0; k < Kc; k++) {
        const float* fk = f[ln][k];
        float p0 = w0*fk[0] + w1*fk[3] + w2*fk[6];
        float p1 = w0*fk[1] + w1*fk[4] + w2*fk[7];
        float p2 = w0*fk[2] + w1*fk[5] + w2*fk[8];
        float nr = sqrtf(p0*p0 + p1*p1 + p2*p2) + VEPS;
        sn += nr; sn2 += nr*nr;
    }
    red[ln][c] = sn; red[ln][64 + c] = sn2;
    __syncthreads();
    if (t < 64) {
        atomicAdd(&g_s1[t],      (double)red[0][t]      + (double)red[1][t]);
        atomicAdd(&g_s1[64 + t], (double)red[0][64 + t] + (double)red[1][64 + t]);
    }
}

__global__ __launch_bounds__(128) void block1_apply(const float* __restrict__ x,
                                                    const float* __restrict__ W1,
                                                    const float* __restrict__ D1,
                                                    const float* __restrict__ g1,
                                                    const float* __restrict__ b1) {
    int b = blockIdx.y, n0 = blockIdx.x * 2;
    __shared__ float f[2][Kc][9];
    build_f(x, b, n0, f);
    __syncthreads();
    int t = threadIdx.x;
    int ln = t >> 6, c = t & 63;
    float w0 = W1[c*3+0], w1 = W1[c*3+1], w2 = W1[c*3+2];
    float e0 = D1[c*3+0], e1 = D1[c*3+1], e2 = D1[c*3+2];
    float ga = g1[c], be = b1[c], mu = g_mu[c], rs = g_rstd[c];
    float a0 = 0.f, a1 = 0.f, a2 = 0.f;
    #pragma unroll
    for (int k = 0; k < Kc; k++) {
        const float* fk = f[ln][k];
        float p0 = w0*fk[0] + w1*fk[3] + w2*fk[6];
        float p1 = w0*fk[1] + w1*fk[4] + w2*fk[7];
        float p2 = w0*fk[2] + w1*fk[5] + w2*fk[8];
        float nr = sqrtf(p0*p0 + p1*p1 + p2*p2) + VEPS;
        float sc = (ga*(nr - mu)*rs + be) / nr;
        p0 *= sc; p1 *= sc; p2 *= sc;
        float d0 = e0*fk[0] + e1*fk[3] + e2*fk[6];
        float d1 = e0*fk[1] + e1*fk[4] + e2*fk[7];
        float d2 = e0*fk[2] + e1*fk[5] + e2*fk[8];
        float dot = p0*d0 + p1*d1 + p2*d2;
        if (dot < 0.f) {
            float s2 = dot / (d0*d0 + d1*d1 + d2*d2 + VEPS);
            p0 -= s2*d0; p1 -= s2*d1; p2 -= s2*d2;
        }
        a0 += p0; a1 += p1; a2 += p2;
    }
    size_t bn = (size_t)b*Nc + n0 + ln;
    const float inv = 1.f / (float)Kc;
    g_bufA[(bn*3 + 0)*64 + c] = a0 * inv;
    g_bufA[(bn*3 + 1)*64 + c] = a1 * inv;
    g_bufA[(bn*3 + 2)*64 + c] = a2 * inv;
}

// --------------------------- finalize stats ---------------------------------
__global__ void finalize_stats(int which, int C, double cnt) {
    const double* s = (which == 1) ? g_s1 : (which == 2) ? g_s2
                    : (which == 3) ? g_s3 : g_s4;
    int c = threadIdx.x;
    if (c >= C) return;
    double mu  = s[c] / cnt;
    double var = s[C + c] / cnt - mu*mu;
    g_mu[c]   = (float)mu;
    g_rstd[c] = (float)(1.0 / sqrt(var + (double)BNEPS));
}

// --------------------------- layers 2-4: p/d GEMM + norm stats --------------
template<int COUT, int SRC, int WHICH>
__global__ __launch_bounds__(256) void gemm_pd(const float* __restrict__ W,
                                               const float* __restrict__ D) {
    const int CIN = 64;
    const float* __restrict__ h = (SRC == 0) ? g_bufA : g_bufB;
    double* sums = (WHICH == 2) ? g_s2 : (WHICH == 3) ? g_s3 : g_s4;

    int bn0 = blockIdx.x * 16;
    int tid = threadIdx.x;
    int ridx = tid >> 4;
    int cidx = tid & 15;
    const int CJ = COUT / 16;

    float ap[3][CJ], ad[3][CJ];
    #pragma unroll
    for (int c2 = 0; c2 < 3; c2++)
        #pragma unroll
        for (int j = 0; j < CJ; j++) { ap[c2][j] = 0.f; ad[c2][j] = 0.f; }

    __shared__ float hs[48][33];
    __shared__ float ws[COUT][33];
    __shared__ float ds_[COUT][33];

    for (int k0 = 0; k0 < CIN; k0 += 32) {
        for (int e = tid; e < 48*32; e += 256) {
            int r = e >> 5, kk = e & 31;
            hs[r][kk] = h[((size_t)bn0*3 + r)*CIN + k0 + kk];
        }
        for (int e = tid; e < COUT*32; e += 256) {
            int cc = e >> 5, kk = e & 31;
            ws[cc][kk]  = W[cc*CIN + k0 + kk];
            ds_[cc][kk] = D[cc*CIN + k0 + kk];
        }
        __syncthreads();
        #pragma unroll 8
        for (int kk = 0; kk < 32; kk++) {
            float h0 = hs[ridx*3 + 0][kk];
            float h1 = hs[ridx*3 + 1][kk];
            float h2 = hs[ridx*3 + 2][kk];
            #pragma unroll
            for (int j = 0; j < CJ; j++) {
                int cc = cidx + 16*j;
                float w = ws[cc][kk], dd = ds_[cc][kk];
                ap[0][j] += h0*w;  ap[1][j] += h1*w;  ap[2][j] += h2*w;
                ad[0][j] += h0*dd; ad[1][j] += h1*dd; ad[2][j] += h2*dd;
            }
        }
        __syncthreads();
    }

    __shared__ float ssum[COUT], ssum2[COUT];
    if (tid < COUT) { ssum[tid] = 0.f; ssum2[tid] = 0.f; }
    __syncthreads();

    size_t row = ((size_t)bn0 + ridx) * 3;
    #pragma unroll
    for (int j = 0; j < CJ; j++) {
        int cc = cidx + 16*j;
        float nr = sqrtf(ap[0][j]*ap[0][j] + ap[1][j]*ap[1][j] + ap[2][j]*ap[2][j]) + VEPS;
        atomicAdd(&ssum[cc], nr);
        atomicAdd(&ssum2[cc], nr*nr);
        g_p[(row + 0)*COUT + cc] = ap[0][j];
        g_p[(row + 1)*COUT + cc] = ap[1][j];
        g_p[(row + 2)*COUT + cc] = ap[2][j];
        g_d[(row + 0)*COUT + cc] = ad[0][j];
        g_d[(row + 1)*COUT + cc] = ad[1][j];
        g_d[(row + 2)*COUT + cc] = ad[2][j];
    }
    __syncthreads();
    if (tid < COUT) {
        atomicAdd(&sums[tid],        (double)ssum[tid]);
        atomicAdd(&sums[COUT + tid], (double)ssum2[tid]);
    }
}

// --------------------------- apply BN + VN-leaky -----------------------------
template<int COUT, int DST, int PAD>
__global__ __launch_bounds__(256) void apply_bn_leaky(const float* __restrict__ ga,
                                                      const float* __restrict__ be) {
    float* __restrict__ hout = (DST == 0) ? g_bufA : g_bufB;
    int i = blockIdx.x * 256 + threadIdx.x;
    if (i >= BN * COUT) return;
    int bn = i / COUT, c = i % COUT;
    size_t r = (size_t)bn * 3;
    float p0 = g_p[(r+0)*COUT + c], p1 = g_p[(r+1)*COUT + c], p2 = g_p[(r+2)*COUT + c];
    float nr = sqrtf(p0*p0 + p1*p1 + p2*p2) + VEPS;
    float sc = (ga[c]*(nr - g_mu[c])*g_rstd[c] + be[c]) / nr;
    p0 *= sc; p1 *= sc; p2 *= sc;
    float d0 = g_d[(r+0)*COUT + c], d1 = g_d[(r+1)*COUT + c], d2 = g_d[(r+2)*COUT + c];
    float dot = p0*d0 + p1*d1 + p2*d2;
    if (dot < 0.f) {
        float s2 = dot / (d0*d0 + d1*d1 + d2*d2 + VEPS);
        p0 -= s2*d0; p1 -= s2*d1; p2 -= s2*d2;
    }
    size_t ro = (size_t)bn * (PAD ? 4 : 3);
    hout[(ro+0)*COUT + c] = p0;
    hout[(ro+1)*COUT + c] = p1;
    hout[(ro+2)*COUT + c] = p2;
    if (PAD) hout[(ro+3)*COUT + c] = 0.f;
}

// --------------------------- conv5: mma.sync tf32 (3xTF32) + fused epilogue --
// A = g_bufB padded [65536,128], B = W5 [1024,128], C = A @ B^T never stored.
// Block tile 128x128, 8 warps (2x4), warp tile 64x32 via m16n8k8.
// Smem (uint32): per stage {AH, AL, BH, BL} each 128x36 (pad-> conflict-free),
// 2 stages; accf (float[128*8]) after.
#define C5_TILE   4608                    // 128*36
#define C5_STAGE  (4*C5_TILE)             // 18432
#define C5_ACCOFF (2*C5_STAGE)            // 36864 (uint32 index)
#define C5_SMEM   (C5_ACCOFF*4 + 1024*4)  // 151552 bytes

__global__ __launch_bounds__(256) void conv5_mma(const float* __restrict__ W5) {
    extern __shared__ uint32_t sm[];
    float* accf = (float*)(sm + C5_ACCOFF);

    const int tid  = threadIdx.x;
    const int lane = tid & 31, warp = tid >> 5;
    const int grp  = lane >> 2, tig = lane & 3;
    const int warp_m = warp >> 2, warp_n = warp & 3;
    const int m0 = blockIdx.x * 128;
    const int c0 = blockIdx.y * 128;

    float acc[4][4][4];
    #pragma unroll
    for (int mt = 0; mt < 4; mt++)
        #pragma unroll
        for (int nt = 0; nt < 4; nt++)
            #pragma unroll
            for (int rgi = 0; rgi < 4; rgi++) acc[mt][nt][rgi] = 0.f;

    for (int i = tid; i < 1024; i += 256) accf[i] = 0.f;

    float4 av[4], bv[4];
    // ---- chunk loader (global -> regs) ----
    #define LOAD_CHUNK(kc) do { \
        _Pragma("unroll") \
        for (int i = 0; i < 4; i++) { \
            int e = tid + i*256, r = e >> 3, q = e & 7; \
            av[i] = *(const float4*)(g_bufB + (size_t)(m0 + r)*128 + (kc)*32 + q*4); \
            bv[i] = *(const float4*)(W5     + (size_t)(c0 + r)*128 + (kc)*32 + q*4); \
        } } while (0)
    // ---- regs -> smem (split hi/lo tf32) ----
    #define CVT_STORE(s) do { \
        uint32_t* base = sm + (s)*C5_STAGE; \
        _Pragma("unroll") \
        for (int i = 0; i < 4; i++) { \
            int e = tid + i*256, r = e >> 3, q = e & 7; \
            int idx = r*36 + q*4; \
            uint4 hi, lo; \
            hi.x = f2tf32(av[i].x); lo.x = f2tf32(av[i].x - __uint_as_float(hi.x)); \
            hi.y = f2tf32(av[i].y); lo.y = f2tf32(av[i].y - __uint_as_float(hi.y)); \
            hi.z = f2tf32(av[i].z); lo.z = f2tf32(av[i].z - __uint_as_float(hi.z)); \
            hi.w = f2tf32(av[i].w); lo.w = f2tf32(av[i].w - __uint_as_float(hi.w)); \
            *(uint4*)(base + idx)            = hi; \
            *(uint4*)(base + C5_TILE + idx)  = lo; \
            hi.x = f2tf32(bv[i].x); lo.x = f2tf32(bv[i].x - __uint_as_float(hi.x)); \
            hi.y = f2tf32(bv[i].y); lo.y = f2tf32(bv[i].y - __uint_as_float(hi.y)); \
            hi.z = f2tf32(bv[i].z); lo.z = f2tf32(bv[i].z - __uint_as_float(hi.z)); \
            hi.w = f2tf32(bv[i].w); lo.w = f2tf32(bv[i].w - __uint_as_float(hi.w)); \
            *(uint4*)(base + 2*C5_TILE + idx) = hi; \
            *(uint4*)(base + 3*C5_TILE + idx) = lo; \
        } } while (0)

    LOAD_CHUNK(0);
    CVT_STORE(0);
    __syncthreads();

    const int abase = (warp_m*64 + grp)*36 + tig;
    const int bbase = (warp_n*32 + grp)*36 + tig;

    for (int kc = 0; kc < 4; kc++) {
        if (kc < 3) LOAD_CHUNK(kc + 1);

        const uint32_t* AH = sm + (kc & 1)*C5_STAGE;
        const uint32_t* AL = AH + C5_TILE;
        const uint32_t* BH = AH + 2*C5_TILE;
        const uint32_t* BL = AH + 3*C5_TILE;
        #pragma unroll
        for (int ks = 0; ks < 4; ks++) {
            uint32_t bh[4][2], bl[4][2];
            #pragma unroll
            for (int nt = 0; nt < 4; nt++) {
                int o = bbase + nt*8*36 + ks*8;
                bh[nt][0] = BH[o]; bh[nt][1] = BH[o+4];
                bl[nt][0] = BL[o]; bl[nt][1] = BL[o+4];
            }
            #pragma unroll
            for (int mt = 0; mt < 4; mt++) {
                int o = abase + mt*16*36 + ks*8;
                uint32_t ah[4] = { AH[o], AH[o + 8*36], AH[o + 4], AH[o + 8*36 + 4] };
                uint32_t al[4] = { AL[o], AL[o + 8*36], AL[o + 4], AL[o + 8*36 + 4] };
                #pragma unroll
                for (int nt = 0; nt < 4; nt++) {
                    mma16n8k8(acc[mt][nt], ah, bh[nt]);
                    mma16n8k8(acc[mt][nt], al, bh[nt]);
                    mma16n8k8(acc[mt][nt], ah, bl[nt]);
                }
            }
        }
        if (kc < 3) CVT_STORE((kc + 1) & 1);
        __syncthreads();
    }

    // ---- epilogue: rows = point*4 + comp (comp 3 = zero pad) ----
    const int comp = grp & 3;
    #pragma unroll
    for (int nt = 0; nt < 4; nt++) {
        float sv[2]  = {0.f, 0.f}, svn[2] = {0.f, 0.f};
        float sn[2]  = {0.f, 0.f}, sn2[2] = {0.f, 0.f};
        #pragma unroll
        for (int mt = 0; mt < 4; mt++)
            #pragma unroll
            for (int rgi = 0; rgi < 4; rgi++) {
                int par = rgi & 1;
                float v = acc[mt][nt][rgi];
                float q = v*v;
                q += __shfl_xor_sync(0xffffffffu, q, 4);
                q += __shfl_xor_sync(0xffffffffu, q, 8);   // norm^2 of the point
                float nr = sqrtf(q) + VEPS;
                sv[par]  += v;
                svn[par] += v / nr;
                sn[par]  += nr;
                sn2[par] += q;
            }
        #pragma unroll
        for (int par = 0; par < 2; par++) {
            sv[par]  += __shfl_xor_sync(0xffffffffu, sv[par],  16);
            svn[par] += __shfl_xor_sync(0xffffffffu, svn[par], 16);
            sn[par]  += __shfl_xor_sync(0xffffffffu, sn[par],  16);
            sn2[par] += __shfl_xor_sync(0xffffffffu, sn2[par], 16);
            if (lane < 16) {
                int col = warp_n*32 + nt*8 + 2*tig + par;
                if (comp < 3) {
                    atomicAdd(&accf[col*8 + 2 + comp], sv[par]);
                    atomicAdd(&accf[col*8 + 5 + comp], svn[par]);
                }
                if (comp == 0) {
                    atomicAdd(&accf[col*8 + 0], sn[par]);
                    atomicAdd(&accf[col*8 + 1], sn2[par]);
                }
            }
        }
    }
    __syncthreads();

    const int b = (m0 >> 2) / Nc;
    for (int i = tid; i < 1024; i += 256) {
        int c = i >> 3, q = i & 7;
        float vv = accf[i];
        int cg = c0 + c;
        if (q == 0)      atomicAdd(&g_s5[cg],        (double)vv);
        else if (q == 1) atomicAdd(&g_s5[1024 + cg], (double)vv);
        else if (q < 5)  atomicAdd(&g_sumv [(b*1024 + cg)*3 + (q-2)], vv);
        else             atomicAdd(&g_sumvn[(b*1024 + cg)*3 + (q-5)], vv);
    }
    #undef LOAD_CHUNK
    #undef CVT_STORE
}

// --------------------------- final output ------------------------------------
__global__ void final_out(const float* __restrict__ g5, const float* __restrict__ b5,
                          float* __restrict__ out) {
    int c = blockIdx.x * 256 + threadIdx.x;
    if (c >= 1024) return;
    double mu  = g_s5[c]        / (double)BN;
    double var = g_s5[1024 + c] / (double)BN - mu*mu;
    float rs  = (float)(1.0 / sqrt(var + (double)BNEPS));
    float a   = g5[c] * rs;
    float t   = a * (float)mu - b5[c];
    #pragma unroll
    for (int b = 0; b < Bc; b++)
        #pragma unroll
        for (int comp = 0; comp < 3; comp++) {
            int gi = (b*1024 + c)*3 + comp;
            out[gi] = a * (g_sumv[gi] * (1.f/(float)Nc))
                    - t * (g_sumvn[gi] * (1.f/(float)Nc));
        }
}

// ---------------------------------------------------------------------------
extern "C" void kernel_launch(void* const* d_in, const int* in_sizes, int n_in,
                              void* d_out, int out_size) {
    const float* x  = (const float*)d_in[0];
    const float* W1 = (const float*)d_in[1];
    const float* D1 = (const float*)d_in[2];
    const float* g1 = (const float*)d_in[3];
    const float* b1 = (const float*)d_in[4];
    const float* W2 = (const float*)d_in[5];
    const float* D2 = (const float*)d_in[6];
    const float* g2 = (const float*)d_in[7];
    const float* b2 = (const float*)d_in[8];
    const float* W3 = (const float*)d_in[9];
    const float* D3 = (const float*)d_in[10];
    const float* g3 = (const float*)d_in[11];
    const float* b3 = (const float*)d_in[12];
    const float* W4 = (const float*)d_in[13];
    const float* D4 = (const float*)d_in[14];
    const float* g4 = (const float*)d_in[15];
    const float* b4 = (const float*)d_in[16];
    const float* W5 = (const float*)d_in[17];
    const float* g5 = (const float*)d_in[18];
    const float* b5 = (const float*)d_in[19];
    float* out = (float*)d_out;

    cudaFuncSetAttribute(conv5_mma, cudaFuncAttributeMaxDynamicSharedMemorySize, C5_SMEM);

    zero_stats<<<48, 256>>>();
    knn_kernel<<<dim3(Nc/2, Bc), 256>>>(x);

    block1_stats<<<dim3(Nc/2, Bc), 128>>>(x, W1);
    finalize_stats<<<1, 64>>>(1, 64, (double)(Bc*Nc*Kc));
    block1_apply<<<dim3(Nc/2, Bc), 128>>>(x, W1, D1, g1, b1);

    gemm_pd<64, 0, 2><<<BN/16, 256>>>(W2, D2);
    finalize_stats<<<1, 64>>>(2, 64, (double)BN);
    apply_bn_leaky<64, 1, 0><<<(BN*64 + 255)/256, 256>>>(g2, b2);

    gemm_pd<64, 1, 3><<<BN/16, 256>>>(W3, D3);
    finalize_stats<<<1, 64>>>(3, 64, (double)BN);
    apply_bn_leaky<64, 0, 0><<<(BN*64 + 255)/256, 256>>>(g3, b3);

    gemm_pd<128, 0, 4><<<BN/16, 256>>>(W4, D4);
    finalize_stats<<<1, 128>>>(4, 128, (double)BN);
    apply_bn_leaky<128, 1, 1><<<(BN*128 + 255)/256, 256>>>(g4, b4);

    conv5_mma<<<dim3(65536/128, 1024/128), 256, C5_SMEM>>>(W5);
    final_out<<<4, 256>>>(g5, b5, out);
}

// round 4
// speedup vs baseline: 1.1954x; 1.1954x over previous
#include <cuda_runtime.h>
#include <math.h>
#include <stdint.h>

#define Bc   4
#define Nc   4096
#define Kc   20
#define BN   (Bc*Nc)          // 16384
#define VEPS 1e-6f
#define BNEPS 1e-5f

typedef unsigned long long ull;

// ---------------- persistent device scratch (no allocations allowed) -------
__device__ int    g_idx[Bc*Nc*Kc];
__device__ float  g_bufA[BN*3*128];
__device__ float  g_bufB[BN*3*128];
__device__ float  g_p[BN*3*128];
__device__ float  g_d[BN*3*128];
__device__ double g_s1[128];
__device__ double g_s2[128];
__device__ double g_s3[128];
__device__ double g_s4[256];
__device__ double g_s5[2048];            // conv5 norm sums (1024 + 1024)
__device__ float  g_sumv [Bc*1024*3];
__device__ float  g_sumvn[Bc*1024*3];
__device__ float  g_mu[1024];
__device__ float  g_rstd[1024];

// ===================== f32x2 packed helpers ==================================
__device__ __forceinline__ void fma2(ull& d, ull a, ull b) {
    asm("fma.rn.f32x2 %0, %1, %2, %0;" : "+l"(d) : "l"(a), "l"(b));
}
__device__ __forceinline__ ull pack2(float lo, float hi) {
    ull r; asm("mov.b64 %0, {%1, %2};" : "=l"(r) : "f"(lo), "f"(hi)); return r;
}
__device__ __forceinline__ float lo2(ull v) {
    float a, b; asm("mov.b64 {%0, %1}, %2;" : "=f"(a), "=f"(b) : "l"(v)); return a;
}
__device__ __forceinline__ float hi2(ull v) {
    float a, b; asm("mov.b64 {%0, %1}, %2;" : "=f"(a), "=f"(b) : "l"(v)); return b;
}

// ---------------------------------------------------------------------------
__global__ void zero_stats() {
    int i = blockIdx.x * 256 + threadIdx.x;          // grid 48*256 = 12288
    if (i < 128) { g_s1[i] = 0.0; g_s2[i] = 0.0; g_s3[i] = 0.0; }
    if (i < 256) { g_s4[i] = 0.0; }
    if (i < 2048){ g_s5[i] = 0.0; }
    g_sumv[i]  = 0.f;
    g_sumvn[i] = 0.f;
}

// --------------------------- KNN (top-20 by -dist) --------------------------
// 2 queries per block. Rounds of argmax with warp shfl reduce + 4-way merge.
__global__ __launch_bounds__(256) void knn_kernel(const float* __restrict__ x) {
    int b  = blockIdx.y;
    int n0 = blockIdx.x * 2;
    __shared__ float dist[2][Nc];
    __shared__ float bvs[2][4];
    __shared__ int   bis[2][4];
    const float* xb = x + (size_t)b * Nc * 3;

    float q0x = xb[n0*3+0],     q0y = xb[n0*3+1],     q0z = xb[n0*3+2];
    float q1x = xb[(n0+1)*3+0], q1y = xb[(n0+1)*3+1], q1z = xb[(n0+1)*3+2];
    float sq0 = q0x*q0x + q0y*q0y + q0z*q0z;
    float sq1 = q1x*q1x + q1y*q1y + q1z*q1z;

    for (int j = threadIdx.x; j < Nc; j += 256) {
        float ax = xb[j*3+0], ay = xb[j*3+1], az = xb[j*3+2];
        float sqj = ax*ax + ay*ay + az*az;
        dist[0][j] = 2.f*(q0x*ax + q0y*ay + q0z*az) - sq0 - sqj;
        dist[1][j] = 2.f*(q1x*ax + q1y*ay + q1z*az) - sq1 - sqj;
    }
    __syncthreads();

    int half = threadIdx.x >> 7;       // which query
    int lt   = threadIdx.x & 127;
    int wq   = (threadIdx.x >> 5) & 3; // warp within half
    int lane = threadIdx.x & 31;
    float* dh = dist[half];
    int n = n0 + half;

    for (int k = 0; k < Kc; k++) {
        float best = -3.3e38f; int bi = Nc;
        for (int j = lt; j < Nc; j += 128) {
            float v = dh[j];
            if (v > best) { best = v; bi = j; }    // ascending keeps lowest idx on tie
        }
        #pragma unroll
        for (int s = 16; s > 0; s >>= 1) {
            float ov = __shfl_xor_sync(0xffffffffu, best, s);
            int   oi = __shfl_xor_sync(0xffffffffu, bi,   s);
            if (ov > best || (ov == best && oi < bi)) { best = ov; bi = oi; }
        }
        if (lane == 0) { bvs[half][wq] = best; bis[half][wq] = bi; }
        __syncthreads();
        if (lt == 0) {
            float mv = bvs[half][0]; int mi = bis[half][0];
            #pragma unroll
            for (int w = 1; w < 4; w++) {
                float ov = bvs[half][w]; int oi = bis[half][w];
                if (ov > mv || (ov == mv && oi < mi)) { mv = ov; mi = oi; }
            }
            g_idx[((size_t)b*Nc + n)*Kc + k] = mi;
            dh[mi] = -3.4e38f;
        }
        __syncthreads();
    }
}

// --------------------------- block1 (3ch edge feat -> 64) -------------------
__device__ __forceinline__ void build_f(const float* __restrict__ x, int b, int n0,
                                        float f[2][Kc][9]) {
    int t = threadIdx.x;
    if (t < 2*Kc) {
        int ln = t / Kc, k = t % Kc;
        int n = n0 + ln;
        const float* xb = x + (size_t)b * Nc * 3;
        float cx = xb[n*3+0], cy = xb[n*3+1], cz = xb[n*3+2];
        int j = g_idx[((size_t)b*Nc + n)*Kc + k];
        float ax = xb[j*3+0], ay = xb[j*3+1], az = xb[j*3+2];
        f[ln][k][0] = ax - cx; f[ln][k][1] = ay - cy; f[ln][k][2] = az - cz;
        f[ln][k][3] = cx;      f[ln][k][4] = cy;      f[ln][k][5] = cz;
        f[ln][k][6] = ay*cz - az*cy;
        f[ln][k][7] = az*cx - ax*cz;
        f[ln][k][8] = ax*cy - ay*cx;
    }
}

__global__ __launch_bounds__(128) void block1_stats(const float* __restrict__ x,
                                                    const float* __restrict__ W1) {
    int b = blockIdx.y, n0 = blockIdx.x * 2;
    __shared__ float f[2][Kc][9];
    __shared__ float red[2][128];
    build_f(x, b, n0, f);
    __syncthreads();
    int t = threadIdx.x;
    int ln = t >> 6, c = t & 63;
    float w0 = W1[c*3+0], w1 = W1[c*3+1], w2 = W1[c*3+2];
    float sn = 0.f, sn2 = 0.f;
    #pragma unroll
    for (int k = 0; k < Kc; k++) {
        const float* fk = f[ln][k];
        float p0 = w0*fk[0] + w1*fk[3] + w2*fk[6];
        float p1 = w0*fk[1] + w1*fk[4] + w2*fk[7];
        float p2 = w0*fk[2] + w1*fk[5] + w2*fk[8];
        float nr = sqrtf(p0*p0 + p1*p1 + p2*p2) + VEPS;
        sn += nr; sn2 += nr*nr;
    }
    red[ln][c] = sn; red[ln][64 + c] = sn2;
    __syncthreads();
    if (t < 64) {
        atomicAdd(&g_s1[t],      (double)red[0][t]      + (double)red[1][t]);
        atomicAdd(&g_s1[64 + t], (double)red[0][64 + t] + (double)red[1][64 + t]);
    }
}

__global__ __launch_bounds__(128) void block1_apply(const float* __restrict__ x,
                                                    const float* __restrict__ W1,
                                                    const float* __restrict__ D1,
                                                    const float* __restrict__ g1,
                                                    const float* __restrict__ b1) {
    int b = blockIdx.y, n0 = blockIdx.x * 2;
    __shared__ float f[2][Kc][9];
    build_f(x, b, n0, f);
    __syncthreads();
    int t = threadIdx.x;
    int ln = t >> 6, c = t & 63;
    float w0 = W1[c*3+0], w1 = W1[c*3+1], w2 = W1[c*3+2];
    float e0 = D1[c*3+0], e1 = D1[c*3+1], e2 = D1[c*3+2];
    float ga = g1[c], be = b1[c], mu = g_mu[c], rs = g_rstd[c];
    float a0 = 0.f, a1 = 0.f, a2 = 0.f;
    #pragma unroll
    for (int k = 0; k < Kc; k++) {
        const float* fk = f[ln][k];
        float p0 = w0*fk[0] + w1*fk[3] + w2*fk[6];
        float p1 = w0*fk[1] + w1*fk[4] + w2*fk[7];
        float p2 = w0*fk[2] + w1*fk[5] + w2*fk[8];
        float nr = sqrtf(p0*p0 + p1*p1 + p2*p2) + VEPS;
        float sc = (ga*(nr - mu)*rs + be) / nr;
        p0 *= sc; p1 *= sc; p2 *= sc;
        float d0 = e0*fk[0] + e1*fk[3] + e2*fk[6];
        float d1 = e0*fk[1] + e1*fk[4] + e2*fk[7];
        float d2 = e0*fk[2] + e1*fk[5] + e2*fk[8];
        float dot = p0*d0 + p1*d1 + p2*d2;
        if (dot < 0.f) {
            float s2 = dot / (d0*d0 + d1*d1 + d2*d2 + VEPS);
            p0 -= s2*d0; p1 -= s2*d1; p2 -= s2*d2;
        }
        a0 += p0; a1 += p1; a2 += p2;
    }
    size_t bn = (size_t)b*Nc + n0 + ln;
    const float inv = 1.f / (float)Kc;
    g_bufA[(bn*3 + 0)*64 + c] = a0 * inv;
    g_bufA[(bn*3 + 1)*64 + c] = a1 * inv;
    g_bufA[(bn*3 + 2)*64 + c] = a2 * inv;
}

// --------------------------- finalize stats ---------------------------------
__global__ void finalize_stats(int which, int C, double cnt) {
    const double* s = (which == 1) ? g_s1 : (which == 2) ? g_s2
                    : (which == 3) ? g_s3 : g_s4;
    int c = threadIdx.x;
    if (c >= C) return;
    double mu  = s[c] / cnt;
    double var = s[C + c] / cnt - mu*mu;
    g_mu[c]   = (float)mu;
    g_rstd[c] = (float)(1.0 / sqrt(var + (double)BNEPS));
}

// --------------------------- layers 2-4: p/d GEMM (f32x2, {p,d} packed) ------
// h: [(bn*3+comp)*64 + c]. Block: 16 bn rows (48 matrix rows) x COUT channels.
// smem: hsd[kk][48] = {h,h} dup; wd[kk][COUT] = {W, D} packed.
template<int COUT, int SRC, int WHICH>
__global__ __launch_bounds__(256) void gemm_pd(const float* __restrict__ W,
                                               const float* __restrict__ D) {
    const float* __restrict__ h = (SRC == 0) ? g_bufA : g_bufB;
    double* sums = (WHICH == 2) ? g_s2 : (WHICH == 3) ? g_s3 : g_s4;

    __shared__ ull hsd[32*48];
    __shared__ ull wd[32*COUT];
    __shared__ float ssum[COUT], ssum2[COUT];

    int bn0 = blockIdx.x * 16;
    int tid = threadIdx.x;
    int ridx = tid >> 4;      // 0..15 bn row
    int cidx = tid & 15;
    const int CJ = COUT / 16;

    ull accPD[3][CJ];
    #pragma unroll
    for (int c2 = 0; c2 < 3; c2++)
        #pragma unroll
        for (int j = 0; j < CJ; j++) accPD[c2][j] = 0ULL;

    #pragma unroll
    for (int k0 = 0; k0 < 64; k0 += 32) {
        // stage h (48 rows x 32 k), duplicated
        for (int e = tid; e < 48*8; e += 256) {
            int r = e >> 3, q = e & 7;
            float4 hv = *(const float4*)(h + ((size_t)bn0*3 + r)*64 + k0 + q*4);
            hsd[(q*4+0)*48 + r] = pack2(hv.x, hv.x);
            hsd[(q*4+1)*48 + r] = pack2(hv.y, hv.y);
            hsd[(q*4+2)*48 + r] = pack2(hv.z, hv.z);
            hsd[(q*4+3)*48 + r] = pack2(hv.w, hv.w);
        }
        // stage {W,D} packed
        for (int e = tid; e < COUT*8; e += 256) {
            int c = e >> 3, q = e & 7;
            float4 wv = *(const float4*)(W + (size_t)c*64 + k0 + q*4);
            float4 dv = *(const float4*)(D + (size_t)c*64 + k0 + q*4);
            wd[(q*4+0)*COUT + c] = pack2(wv.x, dv.x);
            wd[(q*4+1)*COUT + c] = pack2(wv.y, dv.y);
            wd[(q*4+2)*COUT + c] = pack2(wv.z, dv.z);
            wd[(q*4+3)*COUT + c] = pack2(wv.w, dv.w);
        }
        __syncthreads();
        #pragma unroll 8
        for (int kk = 0; kk < 32; kk++) {
            ull a0 = hsd[kk*48 + ridx*3 + 0];
            ull a1 = hsd[kk*48 + ridx*3 + 1];
            ull a2 = hsd[kk*48 + ridx*3 + 2];
            #pragma unroll
            for (int j = 0; j < CJ; j++) {
                ull b = wd[kk*COUT + cidx + 16*j];
                fma2(accPD[0][j], a0, b);
                fma2(accPD[1][j], a1, b);
                fma2(accPD[2][j], a2, b);
            }
        }
        __syncthreads();
    }

    if (tid < COUT) { ssum[tid] = 0.f; ssum2[tid] = 0.f; }
    __syncthreads();

    size_t row = ((size_t)bn0 + ridx) * 3;
    #pragma unroll
    for (int j = 0; j < CJ; j++) {
        int cc = cidx + 16*j;
        float p0 = lo2(accPD[0][j]), d0 = hi2(accPD[0][j]);
        float p1 = lo2(accPD[1][j]), d1 = hi2(accPD[1][j]);
        float p2 = lo2(accPD[2][j]), d2 = hi2(accPD[2][j]);
        float nr = sqrtf(p0*p0 + p1*p1 + p2*p2) + VEPS;
        atomicAdd(&ssum[cc], nr);
        atomicAdd(&ssum2[cc], nr*nr);
        g_p[(row + 0)*COUT + cc] = p0;
        g_p[(row + 1)*COUT + cc] = p1;
        g_p[(row + 2)*COUT + cc] = p2;
        g_d[(row + 0)*COUT + cc] = d0;
        g_d[(row + 1)*COUT + cc] = d1;
        g_d[(row + 2)*COUT + cc] = d2;
    }
    __syncthreads();
    if (tid < COUT) {
        atomicAdd(&sums[tid],        (double)ssum[tid]);
        atomicAdd(&sums[COUT + tid], (double)ssum2[tid]);
    }
}

// --------------------------- apply BN + VN-leaky -----------------------------
template<int COUT, int DST>
__global__ __launch_bounds__(256) void apply_bn_leaky(const float* __restrict__ ga,
                                                      const float* __restrict__ be) {
    float* __restrict__ hout = (DST == 0) ? g_bufA : g_bufB;
    int i = blockIdx.x * 256 + threadIdx.x;
    if (i >= BN * COUT) return;
    int bn = i / COUT, c = i % COUT;
    size_t r = (size_t)bn * 3;
    float p0 = g_p[(r+0)*COUT + c], p1 = g_p[(r+1)*COUT + c], p2 = g_p[(r+2)*COUT + c];
    float nr = sqrtf(p0*p0 + p1*p1 + p2*p2) + VEPS;
    float sc = (ga[c]*(nr - g_mu[c])*g_rstd[c] + be[c]) / nr;
    p0 *= sc; p1 *= sc; p2 *= sc;
    float d0 = g_d[(r+0)*COUT + c], d1 = g_d[(r+1)*COUT + c], d2 = g_d[(r+2)*COUT + c];
    float dot = p0*d0 + p1*d1 + p2*d2;
    if (dot < 0.f) {
        float s2 = dot / (d0*d0 + d1*d1 + d2*d2 + VEPS);
        p0 -= s2*d0; p1 -= s2*d1; p2 -= s2*d2;
    }
    hout[(r+0)*COUT + c] = p0;
    hout[(r+1)*COUT + c] = p1;
    hout[(r+2)*COUT + c] = p2;
}

// --------------------------- conv5: f32x2 GEMM + fused BN/mean epilogue ------
// A = g_bufB [BN*3, 128] (3 rows per point), B = W5 [1024, 128].
// Block: 32 points (96 rows) x 128 channels; K=128 in 4 chunks of 32,
// double-buffered. A staged transposed [k][comp*32+pt] (point pairs -> LDS.64),
// B staged duplicated {w,w} [k][128].
// Thread (256): ptgrp = tid>>5 (4 points), chgrp = tid&31 (4 channels strided 32).
#define C5_AS_STRIDE 98
#define C5_OFF_AS0 0
#define C5_OFF_AS1 12544                 // 32*98*4
#define C5_OFF_WS0 25088
#define C5_OFF_WS1 57856                 // + 32*128*8
#define C5_OFF_ACC 90624
#define C5_SMEM    94720

__global__ __launch_bounds__(256, 1) void conv5_f2(const float* __restrict__ W5) {
    extern __shared__ char smem[];
    float* As0 = (float*)(smem + C5_OFF_AS0);
    float* As1 = (float*)(smem + C5_OFF_AS1);
    ull*   Ws0 = (ull*)(smem + C5_OFF_WS0);
    ull*   Ws1 = (ull*)(smem + C5_OFF_WS1);
    float* accf = (float*)(smem + C5_OFF_ACC);

    const int tid = threadIdx.x;
    const int ptgrp = tid >> 5;          // 0..7 -> points ptgrp*4 .. +3
    const int chgrp = tid & 31;          // channels chgrp + 32*j
    const int m0 = blockIdx.x * 32;      // first point of tile
    const int c0 = blockIdx.y * 128;     // first channel

    for (int i = tid; i < 1024; i += 256) accf[i] = 0.f;

    ull acc[3][2][4];
    #pragma unroll
    for (int c2 = 0; c2 < 3; c2++)
        #pragma unroll
        for (int pp = 0; pp < 2; pp++)
            #pragma unroll
            for (int j = 0; j < 4; j++) acc[c2][pp][j] = 0ULL;

    float4 av[3], bv[4];
    #define C5_LOAD(kc) do { \
        _Pragma("unroll") \
        for (int i = 0; i < 3; i++) { \
            int e = tid + i*256, r = e >> 3, q = e & 7; \
            av[i] = *(const float4*)(g_bufB + ((size_t)m0*3 + r)*128 + (kc)*32 + q*4); \
        } \
        _Pragma("unroll") \
        for (int i = 0; i < 4; i++) { \
            int e = tid + i*256, r = e >> 3, q = e & 7; \
            bv[i] = *(const float4*)(W5 + (size_t)(c0 + r)*128 + (kc)*32 + q*4); \
        } } while (0)
    #define C5_STORE(As_, Ws_) do { \
        _Pragma("unroll") \
        for (int i = 0; i < 3; i++) { \
            int e = tid + i*256, r = e >> 3, q = e & 7; \
            int pt = r / 3, comp = r % 3; \
            int base = comp*32 + pt; \
            (As_)[(q*4+0)*C5_AS_STRIDE + base] = av[i].x; \
            (As_)[(q*4+1)*C5_AS_STRIDE + base] = av[i].y; \
            (As_)[(q*4+2)*C5_AS_STRIDE + base] = av[i].z; \
            (As_)[(q*4+3)*C5_AS_STRIDE + base] = av[i].w; \
        } \
        _Pragma("unroll") \
        for (int i = 0; i < 4; i++) { \
            int e = tid + i*256, c = e >> 3, q = e & 7; \
            (Ws_)[(q*4+0)*128 + c] = pack2(bv[i].x, bv[i].x); \
            (Ws_)[(q*4+1)*128 + c] = pack2(bv[i].y, bv[i].y); \
            (Ws_)[(q*4+2)*128 + c] = pack2(bv[i].z, bv[i].z); \
            (Ws_)[(q*4+3)*128 + c] = pack2(bv[i].w, bv[i].w); \
        } } while (0)

    C5_LOAD(0);
    C5_STORE(As0, Ws0);
    __syncthreads();

    #pragma unroll
    for (int kc = 0; kc < 4; kc++) {
        if (kc < 3) C5_LOAD(kc + 1);
        const float* A = (kc & 1) ? As1 : As0;
        const ull*   B = (kc & 1) ? Ws1 : Ws0;
        #pragma unroll 8
        for (int k = 0; k < 32; k++) {
            ull a[3][2];
            #pragma unroll
            for (int c2 = 0; c2 < 3; c2++)
                #pragma unroll
                for (int pp = 0; pp < 2; pp++)
                    a[c2][pp] = *(const ull*)(A + k*C5_AS_STRIDE + c2*32 + ptgrp*4 + pp*2);
            ull b[4];
            #pragma unroll
            for (int j = 0; j < 4; j++) b[j] = B[k*128 + chgrp + 32*j];
            #pragma unroll
            for (int c2 = 0; c2 < 3; c2++)
                #pragma unroll
                for (int pp = 0; pp < 2; pp++)
                    #pragma unroll
                    for (int j = 0; j < 4; j++)
                        fma2(acc[c2][pp][j], a[c2][pp], b[j]);
        }
        if (kc < 3) C5_STORE((kc & 1) ? As0 : As1, (kc & 1) ? Ws0 : Ws1);
        __syncthreads();
    }

    // ---- epilogue: all 3 comps of each point live in-thread; no shuffles ----
    #pragma unroll
    for (int j = 0; j < 4; j++) {
        int ch = chgrp + 32*j;
        float sn = 0.f, sn2 = 0.f;
        float sv[3] = {0.f, 0.f, 0.f}, svn[3] = {0.f, 0.f, 0.f};
        #pragma unroll
        for (int pp = 0; pp < 2; pp++)
            #pragma unroll
            for (int side = 0; side < 2; side++) {
                float v0 = side ? hi2(acc[0][pp][j]) : lo2(acc[0][pp][j]);
                float v1 = side ? hi2(acc[1][pp][j]) : lo2(acc[1][pp][j]);
                float v2 = side ? hi2(acc[2][pp][j]) : lo2(acc[2][pp][j]);
                float q  = v0*v0 + v1*v1 + v2*v2;
                float nr = sqrtf(q) + VEPS;
                float inv = 1.f / nr;
                sn += nr; sn2 += q;
                sv[0] += v0; sv[1] += v1; sv[2] += v2;
                svn[0] += v0*inv; svn[1] += v1*inv; svn[2] += v2*inv;
            }
        atomicAdd(&accf[ch*8 + 0], sn);
        atomicAdd(&accf[ch*8 + 1], sn2);
        atomicAdd(&accf[ch*8 + 2], sv[0]);
        atomicAdd(&accf[ch*8 + 3], sv[1]);
        atomicAdd(&accf[ch*8 + 4], sv[2]);
        atomicAdd(&accf[ch*8 + 5], svn[0]);
        atomicAdd(&accf[ch*8 + 6], svn[1]);
        atomicAdd(&accf[ch*8 + 7], svn[2]);
    }
    __syncthreads();

    const int b = m0 / Nc;               // 32 | 4096: blocks never straddle batches
    for (int i = tid; i < 1024; i += 256) {
        int c = i >> 3, q = i & 7;
        float vv = accf[i];
        int cg = c0 + c;
        if (q == 0)      atomicAdd(&g_s5[cg],        (double)vv);
        else if (q == 1) atomicAdd(&g_s5[1024 + cg], (double)vv);
        else if (q < 5)  atomicAdd(&g_sumv [(b*1024 + cg)*3 + (q-2)], vv);
        else             atomicAdd(&g_sumvn[(b*1024 + cg)*3 + (q-5)], vv);
    }
    #undef C5_LOAD
    #undef C5_STORE
}

// --------------------------- final output ------------------------------------
__global__ void final_out(const float* __restrict__ g5, const float* __restrict__ b5,
                          float* __restrict__ out) {
    int c = blockIdx.x * 256 + threadIdx.x;
    if (c >= 1024) return;
    double mu  = g_s5[c]        / (double)BN;
    double var = g_s5[1024 + c] / (double)BN - mu*mu;
    float rs  = (float)(1.0 / sqrt(var + (double)BNEPS));
    float a   = g5[c] * rs;
    float t   = a * (float)mu - b5[c];
    #pragma unroll
    for (int b = 0; b < Bc; b++)
        #pragma unroll
        for (int comp = 0; comp < 3; comp++) {
            int gi = (b*1024 + c)*3 + comp;
            out[gi] = a * (g_sumv[gi] * (1.f/(float)Nc))
                    - t * (g_sumvn[gi] * (1.f/(float)Nc));
        }
}

// ---------------------------------------------------------------------------
extern "C" void kernel_launch(void* const* d_in, const int* in_sizes, int n_in,
                              void* d_out, int out_size) {
    const float* x  = (const float*)d_in[0];
    const float* W1 = (const float*)d_in[1];
    const float* D1 = (const float*)d_in[2];
    const float* g1 = (const float*)d_in[3];
    const float* b1 = (const float*)d_in[4];
    const float* W2 = (const float*)d_in[5];
    const float* D2 = (const float*)d_in[6];
    const float* g2 = (const float*)d_in[7];
    const float* b2 = (const float*)d_in[8];
    const float* W3 = (const float*)d_in[9];
    const float* D3 = (const float*)d_in[10];
    const float* g3 = (const float*)d_in[11];
    const float* b3 = (const float*)d_in[12];
    const float* W4 = (const float*)d_in[13];
    const float* D4 = (const float*)d_in[14];
    const float* g4 = (const float*)d_in[15];
    const float* b4 = (const float*)d_in[16];
    const float* W5 = (const float*)d_in[17];
    const float* g5 = (const float*)d_in[18];
    const float* b5 = (const float*)d_in[19];
    float* out = (float*)d_out;

    cudaFuncSetAttribute(conv5_f2, cudaFuncAttributeMaxDynamicSharedMemorySize, C5_SMEM);

    zero_stats<<<48, 256>>>();
    knn_kernel<<<dim3(Nc/2, Bc), 256>>>(x);

    block1_stats<<<dim3(Nc/2, Bc), 128>>>(x, W1);
    finalize_stats<<<1, 64>>>(1, 64, (double)(Bc*Nc*Kc));
    block1_apply<<<dim3(Nc/2, Bc), 128>>>(x, W1, D1, g1, b1);

    gemm_pd<64, 0, 2><<<BN/16, 256>>>(W2, D2);
    finalize_stats<<<1, 64>>>(2, 64, (double)BN);
    apply_bn_leaky<64, 1><<<(BN*64 + 255)/256, 256>>>(g2, b2);

    gemm_pd<64, 1, 3><<<BN/16, 256>>>(W3, D3);
    finalize_stats<<<1, 64>>>(3, 64, (double)BN);
    apply_bn_leaky<64, 0><<<(BN*64 + 255)/256, 256>>>(g3, b3);

    gemm_pd<128, 0, 4><<<BN/16, 256>>>(W4, D4);
    finalize_stats<<<1, 128>>>(4, 128, (double)BN);
    apply_bn_leaky<128, 1><<<(BN*128 + 255)/256, 256>>>(g4, b4);

    conv5_f2<<<dim3(BN/32, 1024/128), 256, C5_SMEM>>>(W5);
    final_out<<<4, 256>>>(g5, b5, out);
}

// round 5
// speedup vs baseline: 1.7762x; 1.4858x over previous
#include <cuda_runtime.h>
#include <cuda_fp16.h>
#include <math.h>
#include <stdint.h>

#define Bc   4
#define Nc   4096
#define Kc   20
#define BN   (Bc*Nc)          // 16384
#define VEPS 1e-6f
#define BNEPS 1e-5f

// ---------------- persistent device scratch (no allocations allowed) -------
__device__ int    g_idx[Bc*Nc*Kc];
__device__ float  g_bufA[BN*3*128];
__device__ float  g_bufB[BN*4*128];      // padded (4 rows/point) for conv5 MMA
__device__ float  g_p[BN*3*128];
__device__ float  g_d[BN*3*128];
__device__ double g_s1[128];
__device__ double g_s2[128];
__device__ double g_s3[128];
__device__ double g_s4[256];
__device__ double g_s5[2048];            // conv5 norm sums (1024 + 1024)
__device__ float  g_sumv [Bc*1024*3];
__device__ float  g_sumvn[Bc*1024*3];
__device__ float  g_mu[1024];
__device__ float  g_rstd[1024];

// ---------------------------------------------------------------------------
__global__ void zero_stats() {
    int i = blockIdx.x * 256 + threadIdx.x;          // grid 48*256 = 12288
    if (i < 128) { g_s1[i] = 0.0; g_s2[i] = 0.0; g_s3[i] = 0.0; }
    if (i < 256) { g_s4[i] = 0.0; }
    if (i < 2048){ g_s5[i] = 0.0; }
    g_sumv[i]  = 0.f;
    g_sumvn[i] = 0.f;
}

__global__ void dummy_k() { if (threadIdx.x > 1024) g_mu[0] = 0.f; }

// ===================== mma/ldmatrix helpers ==================================
__device__ __forceinline__ uint32_t smem_u32(const void* p) {
    uint32_t a;
    asm("{ .reg .u64 t; cvta.to.shared.u64 t, %1; cvt.u32.u64 %0, t; }" : "=r"(a) : "l"(p));
    return a;
}
__device__ __forceinline__ void ldsm4(uint32_t* r, uint32_t addr) {
    asm volatile("ldmatrix.sync.aligned.m8n8.x4.shared.b16 {%0,%1,%2,%3}, [%4];"
        : "=r"(r[0]), "=r"(r[1]), "=r"(r[2]), "=r"(r[3]) : "r"(addr));
}
__device__ __forceinline__ void mma16816(float* c, const uint32_t* a, uint32_t b0, uint32_t b1) {
    asm volatile("mma.sync.aligned.m16n8k16.row.col.f32.f16.f16.f32 "
        "{%0,%1,%2,%3}, {%4,%5,%6,%7}, {%8,%9}, {%0,%1,%2,%3};"
        : "+f"(c[0]), "+f"(c[1]), "+f"(c[2]), "+f"(c[3])
        : "r"(a[0]), "r"(a[1]), "r"(a[2]), "r"(a[3]), "r"(b0), "r"(b1));
}
__device__ __forceinline__ uint32_t packh2(float lo, float hi) {
    uint32_t r; asm("cvt.rn.f16x2.f32 %0, %1, %2;" : "=r"(r) : "f"(hi), "f"(lo)); return r;
}

// --------------------------- KNN (top-20 by -dist) --------------------------
__global__ __launch_bounds__(256) void knn_kernel(const float* __restrict__ x) {
    int b  = blockIdx.y;
    int n0 = blockIdx.x * 2;
    __shared__ float dist[2][Nc];
    __shared__ float bvs[2][4];
    __shared__ int   bis[2][4];
    const float* xb = x + (size_t)b * Nc * 3;

    float q0x = xb[n0*3+0],     q0y = xb[n0*3+1],     q0z = xb[n0*3+2];
    float q1x = xb[(n0+1)*3+0], q1y = xb[(n0+1)*3+1], q1z = xb[(n0+1)*3+2];
    float sq0 = q0x*q0x + q0y*q0y + q0z*q0z;
    float sq1 = q1x*q1x + q1y*q1y + q1z*q1z;

    for (int j = threadIdx.x; j < Nc; j += 256) {
        float ax = xb[j*3+0], ay = xb[j*3+1], az = xb[j*3+2];
        float sqj = ax*ax + ay*ay + az*az;
        dist[0][j] = 2.f*(q0x*ax + q0y*ay + q0z*az) - sq0 - sqj;
        dist[1][j] = 2.f*(q1x*ax + q1y*ay + q1z*az) - sq1 - sqj;
    }
    __syncthreads();

    int half = threadIdx.x >> 7;
    int lt   = threadIdx.x & 127;
    int wq   = (threadIdx.x >> 5) & 3;
    int lane = threadIdx.x & 31;
    float* dh = dist[half];
    int n = n0 + half;

    for (int k = 0; k < Kc; k++) {
        float best = -3.3e38f; int bi = Nc;
        for (int j = lt; j < Nc; j += 128) {
            float v = dh[j];
            if (v > best) { best = v; bi = j; }
        }
        #pragma unroll
        for (int s = 16; s > 0; s >>= 1) {
            float ov = __shfl_xor_sync(0xffffffffu, best, s);
            int   oi = __shfl_xor_sync(0xffffffffu, bi,   s);
            if (ov > best || (ov == best && oi < bi)) { best = ov; bi = oi; }
        }
        if (lane == 0) { bvs[half][wq] = best; bis[half][wq] = bi; }
        __syncthreads();
        if (lt == 0) {
            float mv = bvs[half][0]; int mi = bis[half][0];
            #pragma unroll
            for (int w = 1; w < 4; w++) {
                float ov = bvs[half][w]; int oi = bis[half][w];
                if (ov > mv || (ov == mv && oi < mi)) { mv = ov; mi = oi; }
            }
            g_idx[((size_t)b*Nc + n)*Kc + k] = mi;
            dh[mi] = -3.4e38f;
        }
        __syncthreads();
    }
}

// --------------------------- block1 (3ch edge feat -> 64) -------------------
__device__ __forceinline__ void build_f(const float* __restrict__ x, int b, int n0,
                                        float f[2][Kc][9]) {
    int t = threadIdx.x;
    if (t < 2*Kc) {
        int ln = t / Kc, k = t % Kc;
        int n = n0 + ln;
        const float* xb = x + (size_t)b * Nc * 3;
        float cx = xb[n*3+0], cy = xb[n*3+1], cz = xb[n*3+2];
        int j = g_idx[((size_t)b*Nc + n)*Kc + k];
        float ax = xb[j*3+0], ay = xb[j*3+1], az = xb[j*3+2];
        f[ln][k][0] = ax - cx; f[ln][k][1] = ay - cy; f[ln][k][2] = az - cz;
        f[ln][k][3] = cx;      f[ln][k][4] = cy;      f[ln][k][5] = cz;
        f[ln][k][6] = ay*cz - az*cy;
        f[ln][k][7] = az*cx - ax*cz;
        f[ln][k][8] = ax*cy - ay*cx;
    }
}

__global__ __launch_bounds__(128) void block1_stats(const float* __restrict__ x,
                                                    const float* __restrict__ W1) {
    int b = blockIdx.y, n0 = blockIdx.x * 2;
    __shared__ float f[2][Kc][9];
    __shared__ float red[2][128];
    build_f(x, b, n0, f);
    __syncthreads();
    int t = threadIdx.x;
    int ln = t >> 6, c = t & 63;
    float w0 = W1[c*3+0], w1 = W1[c*3+1], w2 = W1[c*3+2];
    float sn = 0.f, sn2 = 0.f;
    #pragma unroll
    for (int k = 0; k < Kc; k++) {
        const float* fk = f[ln][k];
        float p0 = w0*fk[0] + w1*fk[3] + w2*fk[6];
        float p1 = w0*fk[1] + w1*fk[4] + w2*fk[7];
        float p2 = w0*fk[2] + w1*fk[5] + w2*fk[8];
        float nr = sqrtf(p0*p0 + p1*p1 + p2*p2) + VEPS;
        sn += nr; sn2 += nr*nr;
    }
    red[ln][c] = sn; red[ln][64 + c] = sn2;
    __syncthreads();
    if (t < 64) {
        atomicAdd(&g_s1[t],      (double)red[0][t]      + (double)red[1][t]);
        atomicAdd(&g_s1[64 + t], (double)red[0][64 + t] + (double)red[1][64 + t]);
    }
}

__global__ __launch_bounds__(128) void block1_apply(const float* __restrict__ x,
                                                    const float* __restrict__ W1,
                                                    const float* __restrict__ D1,
                                                    const float* __restrict__ g1,
                                                    const float* __restrict__ b1) {
    int b = blockIdx.y, n0 = blockIdx.x * 2;
    __shared__ float f[2][Kc][9];
    build_f(x, b, n0, f);
    __syncthreads();
    int t = threadIdx.x;
    int ln = t >> 6, c = t & 63;
    float w0 = W1[c*3+0], w1 = W1[c*3+1], w2 = W1[c*3+2];
    float e0 = D1[c*3+0], e1 = D1[c*3+1], e2 = D1[c*3+2];
    float ga = g1[c], be = b1[c], mu = g_mu[c], rs = g_rstd[c];
    float a0 = 0.f, a1 = 0.f, a2 = 0.f;
    #pragma unroll
    for (int k = 0; k < Kc; k++) {
        const float* fk = f[ln][k];
        float p0 = w0*fk[0] + w1*fk[3] + w2*fk[6];
        float p1 = w0*fk[1] + w1*fk[4] + w2*fk[7];
        float p2 = w0*fk[2] + w1*fk[5] + w2*fk[8];
        float nr = sqrtf(p0*p0 + p1*p1 + p2*p2) + VEPS;
        float sc = (ga*(nr - mu)*rs + be) / nr;
        p0 *= sc; p1 *= sc; p2 *= sc;
        float d0 = e0*fk[0] + e1*fk[3] + e2*fk[6];
        float d1 = e0*fk[1] + e1*fk[4] + e2*fk[7];
        float d2 = e0*fk[2] + e1*fk[5] + e2*fk[8];
        float dot = p0*d0 + p1*d1 + p2*d2;
        if (dot < 0.f) {
            float s2 = dot / (d0*d0 + d1*d1 + d2*d2 + VEPS);
            p0 -= s2*d0; p1 -= s2*d1; p2 -= s2*d2;
        }
        a0 += p0; a1 += p1; a2 += p2;
    }
    size_t bn = (size_t)b*Nc + n0 + ln;
    const float inv = 1.f / (float)Kc;
    g_bufA[(bn*3 + 0)*64 + c] = a0 * inv;
    g_bufA[(bn*3 + 1)*64 + c] = a1 * inv;
    g_bufA[(bn*3 + 2)*64 + c] = a2 * inv;
}

// --------------------------- finalize stats ---------------------------------
__global__ void finalize_stats(int which, int C, double cnt) {
    const double* s = (which == 1) ? g_s1 : (which == 2) ? g_s2
                    : (which == 3) ? g_s3 : g_s4;
    int c = threadIdx.x;
    if (c >= C) return;
    double mu  = s[c] / cnt;
    double var = s[C + c] / cnt - mu*mu;
    g_mu[c]   = (float)mu;
    g_rstd[c] = (float)(1.0 / sqrt(var + (double)BNEPS));
}

// --------------------------- layers 2-4: p/d GEMM + norm stats (scalar) -----
template<int COUT, int SRC, int WHICH>
__global__ __launch_bounds__(256) void gemm_pd(const float* __restrict__ W,
                                               const float* __restrict__ D) {
    const int CIN = 64;
    const float* __restrict__ h = (SRC == 0) ? g_bufA : g_bufB;
    double* sums = (WHICH == 2) ? g_s2 : (WHICH == 3) ? g_s3 : g_s4;

    int bn0 = blockIdx.x * 16;
    int tid = threadIdx.x;
    int ridx = tid >> 4;
    int cidx = tid & 15;
    const int CJ = COUT / 16;

    float ap[3][CJ], ad[3][CJ];
    #pragma unroll
    for (int c2 = 0; c2 < 3; c2++)
        #pragma unroll
        for (int j = 0; j < CJ; j++) { ap[c2][j] = 0.f; ad[c2][j] = 0.f; }

    __shared__ float hs[48][33];
    __shared__ float ws[COUT][33];
    __shared__ float ds_[COUT][33];

    for (int k0 = 0; k0 < CIN; k0 += 32) {
        for (int e = tid; e < 48*32; e += 256) {
            int r = e >> 5, kk = e & 31;
            hs[r][kk] = h[((size_t)bn0*3 + r)*CIN + k0 + kk];
        }
        for (int e = tid; e < COUT*32; e += 256) {
            int cc = e >> 5, kk = e & 31;
            ws[cc][kk]  = W[cc*CIN + k0 + kk];
            ds_[cc][kk] = D[cc*CIN + k0 + kk];
        }
        __syncthreads();
        #pragma unroll 8
        for (int kk = 0; kk < 32; kk++) {
            float h0 = hs[ridx*3 + 0][kk];
            float h1 = hs[ridx*3 + 1][kk];
            float h2 = hs[ridx*3 + 2][kk];
            #pragma unroll
            for (int j = 0; j < CJ; j++) {
                int cc = cidx + 16*j;
                float w = ws[cc][kk], dd = ds_[cc][kk];
                ap[0][j] += h0*w;  ap[1][j] += h1*w;  ap[2][j] += h2*w;
                ad[0][j] += h0*dd; ad[1][j] += h1*dd; ad[2][j] += h2*dd;
            }
        }
        __syncthreads();
    }

    __shared__ float ssum[COUT], ssum2[COUT];
    if (tid < COUT) { ssum[tid] = 0.f; ssum2[tid] = 0.f; }
    __syncthreads();

    size_t row = ((size_t)bn0 + ridx) * 3;
    #pragma unroll
    for (int j = 0; j < CJ; j++) {
        int cc = cidx + 16*j;
        float nr = sqrtf(ap[0][j]*ap[0][j] + ap[1][j]*ap[1][j] + ap[2][j]*ap[2][j]) + VEPS;
        atomicAdd(&ssum[cc], nr);
        atomicAdd(&ssum2[cc], nr*nr);
        g_p[(row + 0)*COUT + cc] = ap[0][j];
        g_p[(row + 1)*COUT + cc] = ap[1][j];
        g_p[(row + 2)*COUT + cc] = ap[2][j];
        g_d[(row + 0)*COUT + cc] = ad[0][j];
        g_d[(row + 1)*COUT + cc] = ad[1][j];
        g_d[(row + 2)*COUT + cc] = ad[2][j];
    }
    __syncthreads();
    if (tid < COUT) {
        atomicAdd(&sums[tid],        (double)ssum[tid]);
        atomicAdd(&sums[COUT + tid], (double)ssum2[tid]);
    }
}

// --------------------------- apply BN + VN-leaky -----------------------------
template<int COUT, int DST, int PAD>
__global__ __launch_bounds__(256) void apply_bn_leaky(const float* __restrict__ ga,
                                                      const float* __restrict__ be) {
    float* __restrict__ hout = (DST == 0) ? g_bufA : g_bufB;
    int i = blockIdx.x * 256 + threadIdx.x;
    if (i >= BN * COUT) return;
    int bn = i / COUT, c = i % COUT;
    size_t r = (size_t)bn * 3;
    float p0 = g_p[(r+0)*COUT + c], p1 = g_p[(r+1)*COUT + c], p2 = g_p[(r+2)*COUT + c];
    float nr = sqrtf(p0*p0 + p1*p1 + p2*p2) + VEPS;
    float sc = (ga[c]*(nr - g_mu[c])*g_rstd[c] + be[c]) / nr;
    p0 *= sc; p1 *= sc; p2 *= sc;
    float d0 = g_d[(r+0)*COUT + c], d1 = g_d[(r+1)*COUT + c], d2 = g_d[(r+2)*COUT + c];
    float dot = p0*d0 + p1*d1 + p2*d2;
    if (dot < 0.f) {
        float s2 = dot / (d0*d0 + d1*d1 + d2*d2 + VEPS);
        p0 -= s2*d0; p1 -= s2*d1; p2 -= s2*d2;
    }
    size_t ro = (size_t)bn * (PAD ? 4 : 3);
    hout[(ro+0)*COUT + c] = p0;
    hout[(ro+1)*COUT + c] = p1;
    hout[(ro+2)*COUT + c] = p2;
    if (PAD) hout[(ro+3)*COUT + c] = 0.f;
}

// --------------------------- conv5: fp16 mma.sync + fused epilogue ----------
// A = g_bufB padded [65536,128] fp32 -> fp16.  B = W5 [1024,128] -> Wh + Wl fp16.
// v = A*(Wh+Wl): weight rounding ~2^-22; h rounding random per point.
// Block tile 128(M) x 128(N), 8 warps (2x4), warp tile 64x32, K=128 (8 ksteps).
// smem: A fp16 [128][256B], Wh, Wl same (32KB each); vsm/accf reuse after.
#define C5_OFF_A   0
#define C5_OFF_BH  32768
#define C5_OFF_BL  65536
#define C5_OFF_ACC 98304
#define C5_SMEM    102400

__device__ __forceinline__ int c5_swz(int row, int b8) {   // b8: byte off in 256B row
    return (row << 8) + (b8 ^ (((row & 3) << 5) | ((row & 4) << 2)));
}

__global__ __launch_bounds__(256, 2) void conv5_hmma(const float* __restrict__ W5) {
    extern __shared__ char smem[];
    const uint32_t sb = smem_u32(smem);
    float* accf = (float*)(smem + C5_OFF_ACC);

    const int tid  = threadIdx.x;
    const int lane = tid & 31, warp = tid >> 5;
    const int grp  = lane >> 2, tig = lane & 3;
    const int warp_m = warp >> 2, warp_n = warp & 3;
    const int m0 = blockIdx.x * 128;     // padded row base (32 points)
    const int c0 = blockIdx.y * 128;

    for (int i = tid; i < 1024; i += 256) accf[i] = 0.f;

    // ---- stage A (fp32 -> fp16, swizzled) ----
    #pragma unroll
    for (int i = 0; i < 16; i++) {
        int e = tid + i*256, r = e >> 5, q = e & 31;
        float4 v = *(const float4*)(g_bufB + (size_t)(m0 + r)*128 + q*4);
        uint2 hv = make_uint2(packh2(v.x, v.y), packh2(v.z, v.w));
        *(uint2*)(smem + C5_OFF_A + c5_swz(r, q*8)) = hv;
    }
    // ---- stage B (split into Wh + Wl fp16, swizzled) ----
    #pragma unroll
    for (int i = 0; i < 16; i++) {
        int e = tid + i*256, r = e >> 5, q = e & 31;
        float4 v = *(const float4*)(W5 + (size_t)(c0 + r)*128 + q*4);
        __half hx = __float2half_rn(v.x), hy = __float2half_rn(v.y);
        __half hz = __float2half_rn(v.z), hw = __float2half_rn(v.w);
        float lx = v.x - __half2float(hx), ly = v.y - __half2float(hy);
        float lz = v.z - __half2float(hz), lw = v.w - __half2float(hw);
        int sw = c5_swz(r, q*8);
        *(uint2*)(smem + C5_OFF_BH + sw) =
            make_uint2(packh2(__half2float(hx), __half2float(hy)),
                       packh2(__half2float(hz), __half2float(hw)));
        *(uint2*)(smem + C5_OFF_BL + sw) = make_uint2(packh2(lx, ly), packh2(lz, lw));
    }
    __syncthreads();

    // ---- precompute ldmatrix lane addresses ----
    uint32_t PA[4], XA[4];
    #pragma unroll
    for (int mt = 0; mt < 4; mt++) {
        int row = warp_m*64 + mt*16 + (lane & 15);
        XA[mt] = (row & 3) << 5;
        PA[mt] = sb + C5_OFF_A + row*256 + ((lane & 16) ^ ((row & 4) << 2));
    }
    uint32_t PBh[2], PBl[2], XB[2];
    #pragma unroll
    for (int p = 0; p < 2; p++) {
        int ch = warp_n*32 + p*16 + ((lane & 16) >> 1) + (lane & 7);
        XB[p]  = (ch & 3) << 5;
        uint32_t off = ch*256 + (((lane & 8) << 1) ^ ((ch & 4) << 2));
        PBh[p] = sb + C5_OFF_BH + off;
        PBl[p] = sb + C5_OFF_BL + off;
    }

    float acc[4][4][4];
    #pragma unroll
    for (int mt = 0; mt < 4; mt++)
        #pragma unroll
        for (int nt = 0; nt < 4; nt++)
            #pragma unroll
            for (int r4 = 0; r4 < 4; r4++) acc[mt][nt][r4] = 0.f;

    // ---- mainloop: 8 ksteps ----
    #pragma unroll
    for (int ks = 0; ks < 8; ks++) {
        uint32_t a[4][4], bh[2][4], bl[2][4];
        #pragma unroll
        for (int mt = 0; mt < 4; mt++) ldsm4(a[mt], PA[mt] + ((ks*32) ^ XA[mt]));
        #pragma unroll
        for (int p = 0; p < 2; p++) {
            ldsm4(bh[p], PBh[p] + ((ks*32) ^ XB[p]));
            ldsm4(bl[p], PBl[p] + ((ks*32) ^ XB[p]));
        }
        #pragma unroll
        for (int mt = 0; mt < 4; mt++)
            #pragma unroll
            for (int nt = 0; nt < 4; nt++) {
                int p = nt >> 1, ix = (nt & 1) * 2;
                mma16816(acc[mt][nt], a[mt], bh[p][ix], bh[p][ix+1]);
                mma16816(acc[mt][nt], a[mt], bl[p][ix], bl[p][ix+1]);
            }
    }
    __syncthreads();

    // ---- epilogue: transpose acc into smem [col][133 rows], then reduce ----
    float* vsm = (float*)smem;           // 128*133*4 = 68096 B (reuses A/Bh/Bl)
    #pragma unroll
    for (int mt = 0; mt < 4; mt++)
        #pragma unroll
        for (int nt = 0; nt < 4; nt++)
            #pragma unroll
            for (int r4 = 0; r4 < 4; r4++) {
                int row = warp_m*64 + mt*16 + grp + ((r4 & 2) ? 8 : 0);
                int col = warp_n*32 + nt*8 + 2*tig + (r4 & 1);
                vsm[col*133 + row] = acc[mt][nt][r4];
            }
    __syncthreads();

    {
        int c = tid & 127, halfp = tid >> 7;   // 16 points each
        float sn = 0.f, sn2 = 0.f;
        float sv0 = 0.f, sv1 = 0.f, sv2 = 0.f;
        float sw0 = 0.f, sw1 = 0.f, sw2 = 0.f;
        const float* vc = vsm + c*133 + halfp*64;
        #pragma unroll
        for (int i = 0; i < 16; i++) {
            float v0 = vc[i*4 + 0], v1 = vc[i*4 + 1], v2 = vc[i*4 + 2];
            float q  = v0*v0 + v1*v1 + v2*v2;
            float nr = sqrtf(q) + VEPS;
            float inv = 1.f / nr;
            sn += nr; sn2 += q;
            sv0 += v0; sv1 += v1; sv2 += v2;
            sw0 += v0*inv; sw1 += v1*inv; sw2 += v2*inv;
        }
        atomicAdd(&accf[c*8 + 0], sn);
        atomicAdd(&accf[c*8 + 1], sn2);
        atomicAdd(&accf[c*8 + 2], sv0);
        atomicAdd(&accf[c*8 + 3], sv1);
        atomicAdd(&accf[c*8 + 4], sv2);
        atomicAdd(&accf[c*8 + 5], sw0);
        atomicAdd(&accf[c*8 + 6], sw1);
        atomicAdd(&accf[c*8 + 7], sw2);
    }
    __syncthreads();

    const int b = blockIdx.x / 128;      // 32 pts/block, 4096 pts/batch
    for (int i = tid; i < 1024; i += 256) {
        int c = i >> 3, q = i & 7;
        float vv = accf[i];
        int cg = c0 + c;
        if (q == 0)      atomicAdd(&g_s5[cg],        (double)vv);
        else if (q == 1) atomicAdd(&g_s5[1024 + cg], (double)vv);
        else if (q < 5)  atomicAdd(&g_sumv [(b*1024 + cg)*3 + (q-2)], vv);
        else             atomicAdd(&g_sumvn[(b*1024 + cg)*3 + (q-5)], vv);
    }
}

// --------------------------- final output ------------------------------------
__global__ void final_out(const float* __restrict__ g5, const float* __restrict__ b5,
                          float* __restrict__ out) {
    int c = blockIdx.x * 256 + threadIdx.x;
    if (c >= 1024) return;
    double mu  = g_s5[c]        / (double)BN;
    double var = g_s5[1024 + c] / (double)BN - mu*mu;
    float rs  = (float)(1.0 / sqrt(var + (double)BNEPS));
    float a   = g5[c] * rs;
    float t   = a * (float)mu - b5[c];
    #pragma unroll
    for (int b = 0; b < Bc; b++)
        #pragma unroll
        for (int comp = 0; comp < 3; comp++) {
            int gi = (b*1024 + c)*3 + comp;
            out[gi] = a * (g_sumv[gi] * (1.f/(float)Nc))
                    - t * (g_sumvn[gi] * (1.f/(float)Nc));
        }
}

// ---------------------------------------------------------------------------
extern "C" void kernel_launch(void* const* d_in, const int* in_sizes, int n_in,
                              void* d_out, int out_size) {
    const float* x  = (const float*)d_in[0];
    const float* W1 = (const float*)d_in[1];
    const float* D1 = (const float*)d_in[2];
    const float* g1 = (const float*)d_in[3];
    const float* b1 = (const float*)d_in[4];
    const float* W2 = (const float*)d_in[5];
    const float* D2 = (const float*)d_in[6];
    const float* g2 = (const float*)d_in[7];
    const float* b2 = (const float*)d_in[8];
    const float* W3 = (const float*)d_in[9];
    const float* D3 = (const float*)d_in[10];
    const float* g3 = (const float*)d_in[11];
    const float* b3 = (const float*)d_in[12];
    const float* W4 = (const float*)d_in[13];
    const float* D4 = (const float*)d_in[14];
    const float* g4 = (const float*)d_in[15];
    const float* b4 = (const float*)d_in[16];
    const float* W5 = (const float*)d_in[17];
    const float* g5 = (const float*)d_in[18];
    const float* b5 = (const float*)d_in[19];
    float* out = (float*)d_out;

    cudaFuncSetAttribute(conv5_hmma, cudaFuncAttributeMaxDynamicSharedMemorySize, C5_SMEM);

    zero_stats<<<48, 256>>>();
    // 5 dummies so knn_kernel lands at profiled launch index 6
    for (int i = 0; i < 5; i++) dummy_k<<<1, 32>>>();
    knn_kernel<<<dim3(Nc/2, Bc), 256>>>(x);

    block1_stats<<<dim3(Nc/2, Bc), 128>>>(x, W1);
    finalize_stats<<<1, 64>>>(1, 64, (double)(Bc*Nc*Kc));
    block1_apply<<<dim3(Nc/2, Bc), 128>>>(x, W1, D1, g1, b1);

    gemm_pd<64, 0, 2><<<BN/16, 256>>>(W2, D2);
    finalize_stats<<<1, 64>>>(2, 64, (double)BN);
    apply_bn_leaky<64, 1, 0><<<(BN*64 + 255)/256, 256>>>(g2, b2);

    gemm_pd<64, 1, 3><<<BN/16, 256>>>(W3, D3);
    finalize_stats<<<1, 64>>>(3, 64, (double)BN);
    apply_bn_leaky<64, 0, 0><<<(BN*64 + 255)/256, 256>>>(g3, b3);

    gemm_pd<128, 0, 4><<<BN/16, 256>>>(W4, D4);
    finalize_stats<<<1, 128>>>(4, 128, (double)BN);
    apply_bn_leaky<128, 1, 1><<<(BN*128 + 255)/256, 256>>>(g4, b4);

    conv5_hmma<<<dim3(65536/128, 1024/128), 256, C5_SMEM>>>(W5);
    final_out<<<4, 256>>>(g5, b5, out);
}

// round 6
// speedup vs baseline: 1.9157x; 1.0785x over previous
#include <cuda_runtime.h>
#include <cuda_fp16.h>
#include <math.h>
#include <stdint.h>

#define Bc   4
#define Nc   4096
#define Kc   20
#define BN   (Bc*Nc)          // 16384
#define VEPS 1e-6f
#define BNEPS 1e-5f

// ---------------- persistent device scratch (no allocations allowed) -------
__device__ int    g_idx[Bc*Nc*Kc];
__device__ float  g_bufA[BN*4*128];      // padded h layouts (4 rows/point)
__device__ float  g_bufB[BN*4*128];
__device__ float  g_p[BN*3*128];
__device__ float  g_d[BN*3*128];
__device__ double g_s1[128];
__device__ double g_s2[128];
__device__ double g_s3[128];
__device__ double g_s4[256];
__device__ double g_s5[2048];            // conv5 norm sums (1024 + 1024)
__device__ float  g_sumv [Bc*1024*3];
__device__ float  g_sumvn[Bc*1024*3];

// ---------------------------------------------------------------------------
__global__ void zero_stats() {
    int i = blockIdx.x * 256 + threadIdx.x;          // grid 48*256 = 12288
    if (i < 128) { g_s1[i] = 0.0; g_s2[i] = 0.0; g_s3[i] = 0.0; }
    if (i < 256) { g_s4[i] = 0.0; }
    if (i < 2048){ g_s5[i] = 0.0; }
    g_sumv[i]  = 0.f;
    g_sumvn[i] = 0.f;
}

__global__ void dummy_k() { if (threadIdx.x > 1024) g_sumv[0] = 0.f; }

// ===================== mma/ldmatrix helpers ==================================
__device__ __forceinline__ uint32_t smem_u32(const void* p) {
    uint32_t a;
    asm("{ .reg .u64 t; cvta.to.shared.u64 t, %1; cvt.u32.u64 %0, t; }" : "=r"(a) : "l"(p));
    return a;
}
__device__ __forceinline__ void ldsm4(uint32_t* r, uint32_t addr) {
    asm volatile("ldmatrix.sync.aligned.m8n8.x4.shared.b16 {%0,%1,%2,%3}, [%4];"
        : "=r"(r[0]), "=r"(r[1]), "=r"(r[2]), "=r"(r[3]) : "r"(addr));
}
__device__ __forceinline__ void mma16816(float* c, const uint32_t* a, uint32_t b0, uint32_t b1) {
    asm volatile("mma.sync.aligned.m16n8k16.row.col.f32.f16.f16.f32 "
        "{%0,%1,%2,%3}, {%4,%5,%6,%7}, {%8,%9}, {%0,%1,%2,%3};"
        : "+f"(c[0]), "+f"(c[1]), "+f"(c[2]), "+f"(c[3])
        : "r"(a[0]), "r"(a[1]), "r"(a[2]), "r"(a[3]), "r"(b0), "r"(b1));
}
__device__ __forceinline__ uint32_t packh2(float lo, float hi) {
    uint32_t r; asm("cvt.rn.f16x2.f32 %0, %1, %2;" : "=r"(r) : "f"(hi), "f"(lo)); return r;
}
__device__ __forceinline__ void split8(const float4 v0, const float4 v1,
                                       uint4& hh, uint4& ll) {
    float f[8] = {v0.x, v0.y, v0.z, v0.w, v1.x, v1.y, v1.z, v1.w};
    float hi[8], lo[8];
    #pragma unroll
    for (int i = 0; i < 8; i++) {
        __half h = __float2half_rn(f[i]);
        hi[i] = __half2float(h);
        lo[i] = f[i] - hi[i];
    }
    hh = make_uint4(packh2(hi[0],hi[1]), packh2(hi[2],hi[3]),
                    packh2(hi[4],hi[5]), packh2(hi[6],hi[7]));
    ll = make_uint4(packh2(lo[0],lo[1]), packh2(lo[2],lo[3]),
                    packh2(lo[4],lo[5]), packh2(lo[6],lo[7]));
}

// --------------------------- KNN (top-20 by -dist) --------------------------
__global__ __launch_bounds__(256) void knn_kernel(const float* __restrict__ x) {
    int b  = blockIdx.y;
    int n0 = blockIdx.x * 2;
    __shared__ float dist[2][Nc];
    __shared__ float bvs[2][4];
    __shared__ int   bis[2][4];
    const float* xb = x + (size_t)b * Nc * 3;

    float q0x = xb[n0*3+0],     q0y = xb[n0*3+1],     q0z = xb[n0*3+2];
    float q1x = xb[(n0+1)*3+0], q1y = xb[(n0+1)*3+1], q1z = xb[(n0+1)*3+2];
    float sq0 = q0x*q0x + q0y*q0y + q0z*q0z;
    float sq1 = q1x*q1x + q1y*q1y + q1z*q1z;

    for (int j = threadIdx.x; j < Nc; j += 256) {
        float ax = xb[j*3+0], ay = xb[j*3+1], az = xb[j*3+2];
        float sqj = ax*ax + ay*ay + az*az;
        dist[0][j] = 2.f*(q0x*ax + q0y*ay + q0z*az) - sq0 - sqj;
        dist[1][j] = 2.f*(q1x*ax + q1y*ay + q1z*az) - sq1 - sqj;
    }
    __syncthreads();

    int half = threadIdx.x >> 7;
    int lt   = threadIdx.x & 127;
    int wq   = (threadIdx.x >> 5) & 3;
    int lane = threadIdx.x & 31;
    float* dh = dist[half];
    int n = n0 + half;

    for (int k = 0; k < Kc; k++) {
        float best = -3.3e38f; int bi = Nc;
        for (int j = lt; j < Nc; j += 128) {
            float v = dh[j];
            if (v > best) { best = v; bi = j; }
        }
        #pragma unroll
        for (int s = 16; s > 0; s >>= 1) {
            float ov = __shfl_xor_sync(0xffffffffu, best, s);
            int   oi = __shfl_xor_sync(0xffffffffu, bi,   s);
            if (ov > best || (ov == best && oi < bi)) { best = ov; bi = oi; }
        }
        if (lane == 0) { bvs[half][wq] = best; bis[half][wq] = bi; }
        __syncthreads();
        if (lt == 0) {
            float mv = bvs[half][0]; int mi = bis[half][0];
            #pragma unroll
            for (int w = 1; w < 4; w++) {
                float ov = bvs[half][w]; int oi = bis[half][w];
                if (ov > mv || (ov == mv && oi < mi)) { mv = ov; mi = oi; }
            }
            g_idx[((size_t)b*Nc + n)*Kc + k] = mi;
            dh[mi] = -3.4e38f;
        }
        __syncthreads();
    }
}

// --------------------------- block1 (3ch edge feat -> 64) -------------------
__device__ __forceinline__ void build_f(const float* __restrict__ x, int b, int n0,
                                        float f[2][Kc][9]) {
    int t = threadIdx.x;
    if (t < 2*Kc) {
        int ln = t / Kc, k = t % Kc;
        int n = n0 + ln;
        const float* xb = x + (size_t)b * Nc * 3;
        float cx = xb[n*3+0], cy = xb[n*3+1], cz = xb[n*3+2];
        int j = g_idx[((size_t)b*Nc + n)*Kc + k];
        float ax = xb[j*3+0], ay = xb[j*3+1], az = xb[j*3+2];
        f[ln][k][0] = ax - cx; f[ln][k][1] = ay - cy; f[ln][k][2] = az - cz;
        f[ln][k][3] = cx;      f[ln][k][4] = cy;      f[ln][k][5] = cz;
        f[ln][k][6] = ay*cz - az*cy;
        f[ln][k][7] = az*cx - ax*cz;
        f[ln][k][8] = ax*cy - ay*cx;
    }
}

__global__ __launch_bounds__(128) void block1_stats(const float* __restrict__ x,
                                                    const float* __restrict__ W1) {
    int b = blockIdx.y, n0 = blockIdx.x * 2;
    __shared__ float f[2][Kc][9];
    __shared__ float red[2][128];
    build_f(x, b, n0, f);
    __syncthreads();
    int t = threadIdx.x;
    int ln = t >> 6, c = t & 63;
    float w0 = W1[c*3+0], w1 = W1[c*3+1], w2 = W1[c*3+2];
    float sn = 0.f, sn2 = 0.f;
    #pragma unroll
    for (int k = 0; k < Kc; k++) {
        const float* fk = f[ln][k];
        float p0 = w0*fk[0] + w1*fk[3] + w2*fk[6];
        float p1 = w0*fk[1] + w1*fk[4] + w2*fk[7];
        float p2 = w0*fk[2] + w1*fk[5] + w2*fk[8];
        float nr = sqrtf(p0*p0 + p1*p1 + p2*p2) + VEPS;
        sn += nr; sn2 += nr*nr;
    }
    red[ln][c] = sn; red[ln][64 + c] = sn2;
    __syncthreads();
    if (t < 64) {
        atomicAdd(&g_s1[t],      (double)red[0][t]      + (double)red[1][t]);
        atomicAdd(&g_s1[64 + t], (double)red[0][64 + t] + (double)red[1][64 + t]);
    }
}

__global__ __launch_bounds__(128) void block1_apply(const float* __restrict__ x,
                                                    const float* __restrict__ W1,
                                                    const float* __restrict__ D1,
                                                    const float* __restrict__ g1,
                                                    const float* __restrict__ b1) {
    int b = blockIdx.y, n0 = blockIdx.x * 2;
    __shared__ float f[2][Kc][9];
    build_f(x, b, n0, f);
    __syncthreads();
    int t = threadIdx.x;
    int ln = t >> 6, c = t & 63;
    float w0 = W1[c*3+0], w1 = W1[c*3+1], w2 = W1[c*3+2];
    float e0 = D1[c*3+0], e1 = D1[c*3+1], e2 = D1[c*3+2];
    // inline finalize from g_s1
    const double cnt = (double)(Bc*Nc*Kc);
    double mud = g_s1[c] / cnt;
    float  mu  = (float)mud;
    float  rs  = rsqrtf((float)(g_s1[64 + c] / cnt - mud*mud) + BNEPS);
    float ga = g1[c], be = b1[c];
    float a0 = 0.f, a1 = 0.f, a2 = 0.f;
    #pragma unroll
    for (int k = 0; k < Kc; k++) {
        const float* fk = f[ln][k];
        float p0 = w0*fk[0] + w1*fk[3] + w2*fk[6];
        float p1 = w0*fk[1] + w1*fk[4] + w2*fk[7];
        float p2 = w0*fk[2] + w1*fk[5] + w2*fk[8];
        float nr = sqrtf(p0*p0 + p1*p1 + p2*p2) + VEPS;
        float sc = (ga*(nr - mu)*rs + be) / nr;
        p0 *= sc; p1 *= sc; p2 *= sc;
        float d0 = e0*fk[0] + e1*fk[3] + e2*fk[6];
        float d1 = e0*fk[1] + e1*fk[4] + e2*fk[7];
        float d2 = e0*fk[2] + e1*fk[5] + e2*fk[8];
        float dot = p0*d0 + p1*d1 + p2*d2;
        if (dot < 0.f) {
            float s2 = dot / (d0*d0 + d1*d1 + d2*d2 + VEPS);
            p0 -= s2*d0; p1 -= s2*d1; p2 -= s2*d2;
        }
        a0 += p0; a1 += p1; a2 += p2;
    }
    size_t bn = (size_t)b*Nc + n0 + ln;
    const float inv = 1.f / (float)Kc;
    g_bufA[(bn*4 + 0)*64 + c] = a0 * inv;
    g_bufA[(bn*4 + 1)*64 + c] = a1 * inv;
    g_bufA[(bn*4 + 2)*64 + c] = a2 * inv;
    g_bufA[(bn*4 + 3)*64 + c] = 0.f;
}

// --------------------------- layers 2-4: HMMA p/d GEMM + stats --------------
// A = h padded [BN*4, 64] fp32 -> Ah+Al fp16.  B = [W;D] stacked -> Bh+Bl.
// 3-pass (AhBh + AlBh + AhBl) ~ fp32 accuracy. Block 128(M) x 128(N), K=64.
#define L_OFF_AH 0
#define L_OFF_AL 16384
#define L_OFF_BH 32768
#define L_OFF_BL 49152
#define L_OFF_SS 68096                   // after vsm 128*133*4
#define L_SMEM   69632

template<int COUT, int SRC, int WHICH>
__global__ __launch_bounds__(256, 2) void gemm_hmma(const float* __restrict__ W,
                                                    const float* __restrict__ D) {
    extern __shared__ char smem[];
    const uint32_t sb = smem_u32(smem);
    const int tid  = threadIdx.x;
    const int lane = tid & 31, warp = tid >> 5;
    const int grp  = lane >> 2, tig = lane & 3;
    const int warp_m = warp >> 2, warp_n = warp & 3;
    const int m0 = blockIdx.x * 128;     // padded row base (32 points)
    const int c0 = blockIdx.y * 128;     // stacked [W;D] column base
    const float* __restrict__ h = (SRC == 0) ? g_bufA : g_bufB;
    double* sums = (WHICH == 2) ? g_s2 : (WHICH == 3) ? g_s3 : g_s4;

    float* ssum = (float*)(smem + L_OFF_SS);
    ssum[tid] = 0.f;                     // 256 floats: [0:128) sum, [128:256) sum2

    // ---- stage A and B, split hi/lo fp16, 128B rows, unit^=(row&7) swizzle --
    #pragma unroll
    for (int i = 0; i < 4; i++) {
        int e = tid + i*256, r = e >> 3, un = e & 7;
        const float* src = h + (size_t)(m0 + r)*64 + un*8;
        uint4 hh, ll;
        split8(*(const float4*)src, *(const float4*)(src + 4), hh, ll);
        uint32_t sw = r*128 + ((un ^ (r & 7)) << 4);
        *(uint4*)(smem + L_OFF_AH + sw) = hh;
        *(uint4*)(smem + L_OFF_AL + sw) = ll;
    }
    #pragma unroll
    for (int i = 0; i < 4; i++) {
        int e = tid + i*256, r = e >> 3, un = e & 7;
        int idx = c0 + r;
        const float* src = (idx < COUT) ? W + (size_t)idx*64 + un*8
                                        : D + (size_t)(idx - COUT)*64 + un*8;
        uint4 hh, ll;
        split8(*(const float4*)src, *(const float4*)(src + 4), hh, ll);
        uint32_t sw = r*128 + ((un ^ (r & 7)) << 4);
        *(uint4*)(smem + L_OFF_BH + sw) = hh;
        *(uint4*)(smem + L_OFF_BL + sw) = ll;
    }
    __syncthreads();

    // ---- fragment addresses ----
    uint32_t RA[4]; int rxa[4];
    const int u_a = (lane >> 4) & 1;
    #pragma unroll
    for (int mt = 0; mt < 4; mt++) {
        int row = warp_m*64 + mt*16 + (lane & 15);
        RA[mt] = sb + L_OFF_AH + row*128;
        rxa[mt] = row & 7;
    }
    uint32_t RB[2]; int rxb[2];
    const int u_b = (lane >> 3) & 1;
    #pragma unroll
    for (int p = 0; p < 2; p++) {
        int ch = warp_n*32 + p*16 + ((lane & 16) >> 1) + (lane & 7);
        RB[p] = sb + L_OFF_BH + ch*128;
        rxb[p] = ch & 7;
    }

    float acc[4][4][4];
    #pragma unroll
    for (int mt = 0; mt < 4; mt++)
        #pragma unroll
        for (int nt = 0; nt < 4; nt++)
            #pragma unroll
            for (int r4 = 0; r4 < 4; r4++) acc[mt][nt][r4] = 0.f;

    // ---- mainloop: 4 ksteps, 3-pass split ----
    #pragma unroll
    for (int ks = 0; ks < 4; ks++) {
        uint32_t ah[4][4], al[4][4], bh[2][4], bl[2][4];
        #pragma unroll
        for (int mt = 0; mt < 4; mt++) {
            uint32_t off = (uint32_t)(((ks*2 + u_a) ^ rxa[mt]) << 4);
            ldsm4(ah[mt], RA[mt] + off);
            ldsm4(al[mt], RA[mt] + 16384 + off);
        }
        #pragma unroll
        for (int p = 0; p < 2; p++) {
            uint32_t off = (uint32_t)(((ks*2 + u_b) ^ rxb[p]) << 4);
            ldsm4(bh[p], RB[p] + off);
            ldsm4(bl[p], RB[p] + 16384 + off);
        }
        #pragma unroll
        for (int mt = 0; mt < 4; mt++)
            #pragma unroll
            for (int nt = 0; nt < 4; nt++) {
                int p = nt >> 1, ix = (nt & 1) * 2;
                mma16816(acc[mt][nt], ah[mt], bh[p][ix], bh[p][ix+1]);
                mma16816(acc[mt][nt], al[mt], bh[p][ix], bh[p][ix+1]);
                mma16816(acc[mt][nt], ah[mt], bl[p][ix], bl[p][ix+1]);
            }
    }
    __syncthreads();

    // ---- transpose acc into vsm [col][133], then per-col reduce/writes ----
    float* vsm = (float*)smem;
    #pragma unroll
    for (int mt = 0; mt < 4; mt++)
        #pragma unroll
        for (int nt = 0; nt < 4; nt++)
            #pragma unroll
            for (int r4 = 0; r4 < 4; r4++) {
                int row = warp_m*64 + mt*16 + grp + ((r4 & 2) ? 8 : 0);
                int col = warp_n*32 + nt*8 + 2*tig + (r4 & 1);
                vsm[col*133 + row] = acc[mt][nt][r4];
            }
    __syncthreads();

    {
        int c = tid & 127, halfp = tid >> 7;     // 16 points each
        int idx = c0 + c;
        bool isP = (idx < COUT);
        int ch = isP ? idx : idx - COUT;
        float* gout = isP ? g_p : g_d;
        float sn = 0.f, sn2 = 0.f;
        const float* vc = vsm + c*133 + halfp*64;
        int bn0 = blockIdx.x*32 + halfp*16;
        #pragma unroll
        for (int i = 0; i < 16; i++) {
            float v0 = vc[i*4 + 0], v1 = vc[i*4 + 1], v2 = vc[i*4 + 2];
            size_t row = (size_t)(bn0 + i) * 3;
            gout[(row + 0)*COUT + ch] = v0;
            gout[(row + 1)*COUT + ch] = v1;
            gout[(row + 2)*COUT + ch] = v2;
            if (isP) {
                float q  = v0*v0 + v1*v1 + v2*v2;
                sn += sqrtf(q) + VEPS; sn2 += q;
            }
        }
        // sn2 must be sum of nr^2 = (sqrt(q)+eps)^2; adjust: nr^2 = q + 2eps*sqrt(q) + eps^2
        // eps=1e-6 -> correction ~1e-6*nr, below fp32 noise; keep q (matches prior rounds).
        if (isP) {
            atomicAdd(&ssum[ch & 127], sn);
            atomicAdd(&ssum[128 + (ch & 127)], sn2);
        }
    }
    __syncthreads();
    if (c0 == 0 && tid < COUT) {
        atomicAdd(&sums[tid],        (double)ssum[tid & 127]);
        atomicAdd(&sums[COUT + tid], (double)ssum[128 + (tid & 127)]);
    }
}

// --------------------------- apply BN + VN-leaky (inline finalize) ----------
template<int COUT, int DST, int WHICH>
__global__ __launch_bounds__(256) void apply_bn_leaky(const float* __restrict__ ga,
                                                      const float* __restrict__ be) {
    float* __restrict__ hout = (DST == 0) ? g_bufA : g_bufB;
    const double* s = (WHICH == 2) ? g_s2 : (WHICH == 3) ? g_s3 : g_s4;
    int i = blockIdx.x * 256 + threadIdx.x;
    if (i >= BN * COUT) return;
    int bn = i / COUT, c = i % COUT;
    const double cnt = (double)BN;
    double mud = s[c] / cnt;
    float  mu  = (float)mud;
    float  rs  = rsqrtf((float)(s[COUT + c] / cnt - mud*mud) + BNEPS);
    size_t r = (size_t)bn * 3;
    float p0 = g_p[(r+0)*COUT + c], p1 = g_p[(r+1)*COUT + c], p2 = g_p[(r+2)*COUT + c];
    float nr = sqrtf(p0*p0 + p1*p1 + p2*p2) + VEPS;
    float sc = (ga[c]*(nr - mu)*rs + be[c]) / nr;
    p0 *= sc; p1 *= sc; p2 *= sc;
    float d0 = g_d[(r+0)*COUT + c], d1 = g_d[(r+1)*COUT + c], d2 = g_d[(r+2)*COUT + c];
    float dot = p0*d0 + p1*d1 + p2*d2;
    if (dot < 0.f) {
        float s2 = dot / (d0*d0 + d1*d1 + d2*d2 + VEPS);
        p0 -= s2*d0; p1 -= s2*d1; p2 -= s2*d2;
    }
    size_t ro = (size_t)bn * 4;
    hout[(ro+0)*COUT + c] = p0;
    hout[(ro+1)*COUT + c] = p1;
    hout[(ro+2)*COUT + c] = p2;
    hout[(ro+3)*COUT + c] = 0.f;
}

// --------------------------- conv5: fp16 mma.sync + fused epilogue ----------
#define C5_OFF_A   0
#define C5_OFF_BH  32768
#define C5_OFF_BL  65536
#define C5_OFF_ACC 98304
#define C5_SMEM    102400

__device__ __forceinline__ int c5_swz(int row, int b8) {   // b8: byte off in 256B row
    return (row << 8) + (b8 ^ (((row & 3) << 5) | ((row & 4) << 2)));
}

__global__ __launch_bounds__(256, 2) void conv5_hmma(const float* __restrict__ W5) {
    extern __shared__ char smem[];
    const uint32_t sb = smem_u32(smem);
    float* accf = (float*)(smem + C5_OFF_ACC);

    const int tid  = threadIdx.x;
    const int lane = tid & 31, warp = tid >> 5;
    const int grp  = lane >> 2, tig = lane & 3;
    const int warp_m = warp >> 2, warp_n = warp & 3;
    const int m0 = blockIdx.x * 128;     // padded row base (32 points)
    const int c0 = blockIdx.y * 128;

    for (int i = tid; i < 1024; i += 256) accf[i] = 0.f;

    #pragma unroll
    for (int i = 0; i < 16; i++) {
        int e = tid + i*256, r = e >> 5, q = e & 31;
        float4 v = *(const float4*)(g_bufB + (size_t)(m0 + r)*128 + q*4);
        uint2 hv = make_uint2(packh2(v.x, v.y), packh2(v.z, v.w));
        *(uint2*)(smem + C5_OFF_A + c5_swz(r, q*8)) = hv;
    }
    #pragma unroll
    for (int i = 0; i < 16; i++) {
        int e = tid + i*256, r = e >> 5, q = e & 31;
        float4 v = *(const float4*)(W5 + (size_t)(c0 + r)*128 + q*4);
        __half hx = __float2half_rn(v.x), hy = __float2half_rn(v.y);
        __half hz = __float2half_rn(v.z), hw = __float2half_rn(v.w);
        float lx = v.x - __half2float(hx), ly = v.y - __half2float(hy);
        float lz = v.z - __half2float(hz), lw = v.w - __half2float(hw);
        int sw = c5_swz(r, q*8);
        *(uint2*)(smem + C5_OFF_BH + sw) =
            make_uint2(packh2(__half2float(hx), __half2float(hy)),
                       packh2(__half2float(hz), __half2float(hw)));
        *(uint2*)(smem + C5_OFF_BL + sw) = make_uint2(packh2(lx, ly), packh2(lz, lw));
    }
    __syncthreads();

    uint32_t PA[4], XA[4];
    #pragma unroll
    for (int mt = 0; mt < 4; mt++) {
        int row = warp_m*64 + mt*16 + (lane & 15);
        XA[mt] = (row & 3) << 5;
        PA[mt] = sb + C5_OFF_A + row*256 + ((lane & 16) ^ ((row & 4) << 2));
    }
    uint32_t PBh[2], PBl[2], XB[2];
    #pragma unroll
    for (int p = 0; p < 2; p++) {
        int ch = warp_n*32 + p*16 + ((lane & 16) >> 1) + (lane & 7);
        XB[p]  = (ch & 3) << 5;
        uint32_t off = ch*256 + (((lane & 8) << 1) ^ ((ch & 4) << 2));
        PBh[p] = sb + C5_OFF_BH + off;
        PBl[p] = sb + C5_OFF_BL + off;
    }

    float acc[4][4][4];
    #pragma unroll
    for (int mt = 0; mt < 4; mt++)
        #pragma unroll
        for (int nt = 0; nt < 4; nt++)
            #pragma unroll
            for (int r4 = 0; r4 < 4; r4++) acc[mt][nt][r4] = 0.f;

    #pragma unroll
    for (int ks = 0; ks < 8; ks++) {
        uint32_t a[4][4], bh[2][4], bl[2][4];
        #pragma unroll
        for (int mt = 0; mt < 4; mt++) ldsm4(a[mt], PA[mt] + ((ks*32) ^ XA[mt]));
        #pragma unroll
        for (int p = 0; p < 2; p++) {
            ldsm4(bh[p], PBh[p] + ((ks*32) ^ XB[p]));
            ldsm4(bl[p], PBl[p] + ((ks*32) ^ XB[p]));
        }
        #pragma unroll
        for (int mt = 0; mt < 4; mt++)
            #pragma unroll
            for (int nt = 0; nt < 4; nt++) {
                int p = nt >> 1, ix = (nt & 1) * 2;
                mma16816(acc[mt][nt], a[mt], bh[p][ix], bh[p][ix+1]);
                mma16816(acc[mt][nt], a[mt], bl[p][ix], bl[p][ix+1]);
            }
    }
    __syncthreads();

    float* vsm = (float*)smem;
    #pragma unroll
    for (int mt = 0; mt < 4; mt++)
        #pragma unroll
        for (int nt = 0; nt < 4; nt++)
            #pragma unroll
            for (int r4 = 0; r4 < 4; r4++) {
                int row = warp_m*64 + mt*16 + grp + ((r4 & 2) ? 8 : 0);
                int col = warp_n*32 + nt*8 + 2*tig + (r4 & 1);
                vsm[col*133 + row] = acc[mt][nt][r4];
            }
    __syncthreads();

    {
        int c = tid & 127, halfp = tid >> 7;
        float sn = 0.f, sn2 = 0.f;
        float sv0 = 0.f, sv1 = 0.f, sv2 = 0.f;
        float sw0 = 0.f, sw1 = 0.f, sw2 = 0.f;
        const float* vc = vsm + c*133 + halfp*64;
        #pragma unroll
        for (int i = 0; i < 16; i++) {
            float v0 = vc[i*4 + 0], v1 = vc[i*4 + 1], v2 = vc[i*4 + 2];
            float q  = v0*v0 + v1*v1 + v2*v2;
            float nr = sqrtf(q) + VEPS;
            float inv = 1.f / nr;
            sn += nr; sn2 += q;
            sv0 += v0; sv1 += v1; sv2 += v2;
            sw0 += v0*inv; sw1 += v1*inv; sw2 += v2*inv;
        }
        atomicAdd(&accf[c*8 + 0], sn);
        atomicAdd(&accf[c*8 + 1], sn2);
        atomicAdd(&accf[c*8 + 2], sv0);
        atomicAdd(&accf[c*8 + 3], sv1);
        atomicAdd(&accf[c*8 + 4], sv2);
        atomicAdd(&accf[c*8 + 5], sw0);
        atomicAdd(&accf[c*8 + 6], sw1);
        atomicAdd(&accf[c*8 + 7], sw2);
    }
    __syncthreads();

    const int b = blockIdx.x / 128;
    for (int i = tid; i < 1024; i += 256) {
        int c = i >> 3, q = i & 7;
        float vv = accf[i];
        int cg = c0 + c;
        if (q == 0)      atomicAdd(&g_s5[cg],        (double)vv);
        else if (q == 1) atomicAdd(&g_s5[1024 + cg], (double)vv);
        else if (q < 5)  atomicAdd(&g_sumv [(b*1024 + cg)*3 + (q-2)], vv);
        else             atomicAdd(&g_sumvn[(b*1024 + cg)*3 + (q-5)], vv);
    }
}

// --------------------------- final output ------------------------------------
__global__ void final_out(const float* __restrict__ g5, const float* __restrict__ b5,
                          float* __restrict__ out) {
    int c = blockIdx.x * 256 + threadIdx.x;
    if (c >= 1024) return;
    double mu  = g_s5[c]        / (double)BN;
    double var = g_s5[1024 + c] / (double)BN - mu*mu;
    float rs  = (float)(1.0 / sqrt(var + (double)BNEPS));
    float a   = g5[c] * rs;
    float t   = a * (float)mu - b5[c];
    #pragma unroll
    for (int b = 0; b < Bc; b++)
        #pragma unroll
        for (int comp = 0; comp < 3; comp++) {
            int gi = (b*1024 + c)*3 + comp;
            out[gi] = a * (g_sumv[gi] * (1.f/(float)Nc))
                    - t * (g_sumvn[gi] * (1.f/(float)Nc));
        }
}

// ---------------------------------------------------------------------------
extern "C" void kernel_launch(void* const* d_in, const int* in_sizes, int n_in,
                              void* d_out, int out_size) {
    const float* x  = (const float*)d_in[0];
    const float* W1 = (const float*)d_in[1];
    const float* D1 = (const float*)d_in[2];
    const float* g1 = (const float*)d_in[3];
    const float* b1 = (const float*)d_in[4];
    const float* W2 = (const float*)d_in[5];
    const float* D2 = (const float*)d_in[6];
    const float* g2 = (const float*)d_in[7];
    const float* b2 = (const float*)d_in[8];
    const float* W3 = (const float*)d_in[9];
    const float* D3 = (const float*)d_in[10];
    const float* g3 = (const float*)d_in[11];
    const float* b3 = (const float*)d_in[12];
    const float* W4 = (const float*)d_in[13];
    const float* D4 = (const float*)d_in[14];
    const float* g4 = (const float*)d_in[15];
    const float* b4 = (const float*)d_in[16];
    const float* W5 = (const float*)d_in[17];
    const float* g5 = (const float*)d_in[18];
    const float* b5 = (const float*)d_in[19];
    float* out = (float*)d_out;

    cudaFuncSetAttribute(conv5_hmma, cudaFuncAttributeMaxDynamicSharedMemorySize, C5_SMEM);
    cudaFuncSetAttribute(gemm_hmma<64, 0, 2>, cudaFuncAttributeMaxDynamicSharedMemorySize, L_SMEM);
    cudaFuncSetAttribute(gemm_hmma<64, 1, 3>, cudaFuncAttributeMaxDynamicSharedMemorySize, L_SMEM);
    cudaFuncSetAttribute(gemm_hmma<128, 0, 4>, cudaFuncAttributeMaxDynamicSharedMemorySize, L_SMEM);

    zero_stats<<<48, 256>>>();                        // launch 0
    for (int i = 0; i < 4; i++) dummy_k<<<1, 32>>>(); // launches 1-4
    knn_kernel<<<dim3(Nc/2, Bc), 256>>>(x);           // launch 5 (ncu -s 5 target)

    block1_stats<<<dim3(Nc/2, Bc), 128>>>(x, W1);
    block1_apply<<<dim3(Nc/2, Bc), 128>>>(x, W1, D1, g1, b1);

    gemm_hmma<64, 0, 2><<<dim3(512, 1), 256, L_SMEM>>>(W2, D2);
    apply_bn_leaky<64, 1, 2><<<(BN*64 + 255)/256, 256>>>(g2, b2);

    gemm_hmma<64, 1, 3><<<dim3(512, 1), 256, L_SMEM>>>(W3, D3);
    apply_bn_leaky<64, 0, 3><<<(BN*64 + 255)/256, 256>>>(g3, b3);

    gemm_hmma<128, 0, 4><<<dim3(512, 2), 256, L_SMEM>>>(W4, D4);
    apply_bn_leaky<128, 1, 4><<<(BN*128 + 255)/256, 256>>>(g4, b4);

    conv5_hmma<<<dim3(65536/128, 1024/128), 256, C5_SMEM>>>(W5);
    final_out<<<4, 256>>>(g5, b5, out);
}